// round 13
// baseline (speedup 1.0000x reference)
#include <cuda_runtime.h>
#include <cuda_bf16.h>
#include <cstdint>
#include <math.h>

#define B_  2
#define T_  2048
#define D_  1024
#define H_  16
#define DH_ 64
#define M_  (B_ * T_)
#define BH_ (B_ * H_)

typedef unsigned long long u64;
typedef unsigned int u32;
typedef __nv_bfloat16 bf16;

// ---------------------------------------------------------------------------
// Generic tensor-core + cp.async PTX (sm_80+, legal under compute_103)
// ---------------------------------------------------------------------------
__device__ __forceinline__ u32 smem_u32(const void* p) {
    u32 a;
    asm("{ .reg .u64 t; cvta.to.shared.u64 t, %1; cvt.u32.u64 %0, t; }"
        : "=r"(a) : "l"(p));
    return a;
}
__device__ __forceinline__ void ldsm4(u32& r0, u32& r1, u32& r2, u32& r3, u32 addr) {
    asm volatile("ldmatrix.sync.aligned.m8n8.x4.shared.b16 {%0,%1,%2,%3}, [%4];"
                 : "=r"(r0), "=r"(r1), "=r"(r2), "=r"(r3) : "r"(addr));
}
__device__ __forceinline__ void mma16816(float* c, const u32* a, const u32* b) {
    asm volatile("mma.sync.aligned.m16n8k16.row.col.f32.bf16.bf16.f32 "
                 "{%0,%1,%2,%3}, {%4,%5,%6,%7}, {%8,%9}, {%0,%1,%2,%3};"
                 : "+f"(c[0]), "+f"(c[1]), "+f"(c[2]), "+f"(c[3])
                 : "r"(a[0]), "r"(a[1]), "r"(a[2]), "r"(a[3]),
                   "r"(b[0]), "r"(b[1]));
}
__device__ __forceinline__ void cpasync16(u32 s, const void* g) {
    asm volatile("cp.async.cg.shared.global [%0], [%1], 16;" :: "r"(s), "l"(g));
}
#define CP_COMMIT()  asm volatile("cp.async.commit_group;" ::: "memory")
#define CP_WAIT(n)   asm volatile("cp.async.wait_group " #n ";" ::: "memory")

__device__ __forceinline__ void split2(float a, float b, u32& hi, u32& lo) {
    __nv_bfloat162 h = __float22bfloat162_rn(make_float2(a, b));
    float2 hf = __bfloat1622float2(h);
    __nv_bfloat162 l = __float22bfloat162_rn(make_float2(a - hf.x, b - hf.y));
    hi = *(u32*)&h;
    lo = *(u32*)&l;
}

// ---------------------------------------------------------------------------
// Scratch (device globals)
// ---------------------------------------------------------------------------
__device__ __align__(16) bf16 g_xhi[M_ * D_];
__device__ __align__(16) bf16 g_xlo[M_ * D_];
__device__ __align__(16) bf16 g_wT[4 * 2 * D_ * D_];        // [w][hi/lo][N][K]
__device__ __align__(16) bf16 g_qhi[BH_ * T_ * DH_];
__device__ __align__(16) bf16 g_qlo[BH_ * T_ * DH_];
__device__ __align__(16) bf16 g_khi[BH_ * T_ * DH_];
__device__ __align__(16) bf16 g_klo[BH_ * T_ * DH_];
__device__ __align__(16) bf16 g_vthi[BH_ * DH_ * T_];       // V^T (B,H,DH,T)
__device__ __align__(16) bf16 g_vtlo[BH_ * DH_ * T_];
__device__ __align__(16) bf16 g_ahi[M_ * D_];
__device__ __align__(16) bf16 g_alo[M_ * D_];

// ---------------------------------------------------------------------------
// Pre-pass kernels (unchanged, validated)
// ---------------------------------------------------------------------------
__global__ __launch_bounds__(256) void split_kernel(const float* __restrict__ src,
                                                    bf16* __restrict__ hi,
                                                    bf16* __restrict__ lo) {
    const int i = (blockIdx.x * 256 + threadIdx.x) * 4;
    const float4 v = *(const float4*)&src[i];
    bf16 h[4], l[4];
    const float f[4] = {v.x, v.y, v.z, v.w};
#pragma unroll
    for (int j = 0; j < 4; j++) {
        h[j] = __float2bfloat16(f[j]);
        l[j] = __float2bfloat16(f[j] - __bfloat162float(h[j]));
    }
    *(uint2*)&hi[i] = *(const uint2*)h;
    *(uint2*)&lo[i] = *(const uint2*)l;
}

__global__ __launch_bounds__(256) void tsplit_kernel(const float* __restrict__ W,
                                                     bf16* __restrict__ hiT,
                                                     bf16* __restrict__ loT) {
    __shared__ float t[32][33];
    const int tx = threadIdx.x & 31;
    const int ty = threadIdx.x >> 5;
    const int bn = blockIdx.x * 32;
    const int bk = blockIdx.y * 32;
#pragma unroll
    for (int i = 0; i < 4; i++)
        t[ty + 8 * i][tx] = W[(size_t)(bk + ty + 8 * i) * D_ + bn + tx];
    __syncthreads();
#pragma unroll
    for (int i = 0; i < 4; i++) {
        const int n = bn + ty + 8 * i;
        const float v = t[tx][ty + 8 * i];
        const bf16 h = __float2bfloat16(v);
        const bf16 l = __float2bfloat16(v - __bfloat162float(h));
        hiT[(size_t)n * D_ + bk + tx] = h;
        loT[(size_t)n * D_ + bk + tx] = l;
    }
}

// ---------------------------------------------------------------------------
// Pipelined HMMA GEMM: BM=128, BN=64, BK=32, 3-stage cp.async.
// Pad stride 40 bf16 (80B: 5 granules, coprime with 8 -> ldmatrix conflict-free)
// MODE 0: f32 row-major. MODE 1: bf16 hi/lo (B,H,T,DH). MODE 2: bf16 hi/lo V^T.
// ---------------------------------------------------------------------------
#define KSTR 40
#define STG_AHI 0
#define STG_ALO 10240
#define STG_WHI 20480
#define STG_WLO 25600
#define STG_SZ  30720
#define NTILE   32
#define GS_TOT  (3 * STG_SZ)   // 92160

template <int MODE>
__global__ __launch_bounds__(256, 2) void hmma_gemm(
    const bf16* __restrict__ Ahi, const bf16* __restrict__ Alo,
    const bf16* __restrict__ WhiT, const bf16* __restrict__ WloT,
    void* __restrict__ Y0, void* __restrict__ Y1) {
    extern __shared__ __align__(16) char gsm[];
    const u32 sbase = smem_u32(gsm);

    const int tid  = threadIdx.x;
    const int wid  = tid >> 5;
    const int lane = tid & 31;
    const int m0 = blockIdx.y * 128;
    const int n0 = blockIdx.x * 64;
    const int wm = (wid >> 1) * 32;
    const int wn = (wid & 1) * 32;

    auto load_tile = [&](int kt, int s) {
        const u32 sb = sbase + (u32)(s * STG_SZ);
        const int kb = kt * 32;
#pragma unroll
        for (int it = 0; it < 2; it++) {
            const int c = tid + it * 256;
            const int row = c >> 2;
            const int c16 = (c & 3) * 8;
            const u32 so = (u32)((row * KSTR + c16) * 2);
            const size_t gi = (size_t)(m0 + row) * D_ + kb + c16;
            cpasync16(sb + STG_AHI + so, Ahi + gi);
            cpasync16(sb + STG_ALO + so, Alo + gi);
        }
        {
            const int row = tid >> 2;
            const int c16 = (tid & 3) * 8;
            const u32 so = (u32)((row * KSTR + c16) * 2);
            const size_t gi = (size_t)(n0 + row) * D_ + kb + c16;
            cpasync16(sb + STG_WHI + so, WhiT + gi);
            cpasync16(sb + STG_WLO + so, WloT + gi);
        }
    };

    // ldmatrix per-lane offsets
    const int aRow = lane & 15;
    const int aK   = (lane >> 4) * 8;
    const int bN   = ((lane >> 4) << 3) | (lane & 7);
    const int bK   = ((lane >> 3) & 1) * 8;
    const u32 aOff = (u32)(((wm + aRow) * KSTR + aK) * 2);
    const u32 bOff = (u32)(((wn + bN) * KSTR + bK) * 2);
    const u32 step16 = 16 * KSTR * 2;   // +16 rows

    float acc[2][4][4];
#pragma unroll
    for (int mt = 0; mt < 2; mt++)
#pragma unroll
        for (int nt = 0; nt < 4; nt++)
#pragma unroll
            for (int r = 0; r < 4; r++) acc[mt][nt][r] = 0.f;

    // prologue: stages 0,1
    load_tile(0, 0); CP_COMMIT();
    load_tile(1, 1); CP_COMMIT();

    for (int kt = 0; kt < NTILE; kt++) {
        const int s = kt % 3;
        if (kt + 2 < NTILE) load_tile(kt + 2, (kt + 2) % 3);
        CP_COMMIT();
        CP_WAIT(2);
        __syncthreads();

        const u32 sb = sbase + (u32)(s * STG_SZ);
        const u32 aHi0 = sb + STG_AHI + aOff;
        const u32 aLo0 = sb + STG_ALO + aOff;
        const u32 bHi0 = sb + STG_WHI + bOff;
        const u32 bLo0 = sb + STG_WLO + bOff;
#pragma unroll
        for (int ks = 0; ks < 2; ks++) {
            const u32 ko = ks * 32;
            u32 ah[2][4], al[2][4], bh[8], bl[8];
            ldsm4(ah[0][0], ah[0][1], ah[0][2], ah[0][3], aHi0 + ko);
            ldsm4(ah[1][0], ah[1][1], ah[1][2], ah[1][3], aHi0 + step16 + ko);
            ldsm4(al[0][0], al[0][1], al[0][2], al[0][3], aLo0 + ko);
            ldsm4(al[1][0], al[1][1], al[1][2], al[1][3], aLo0 + step16 + ko);
            ldsm4(bh[0], bh[1], bh[2], bh[3], bHi0 + ko);
            ldsm4(bh[4], bh[5], bh[6], bh[7], bHi0 + step16 + ko);
            ldsm4(bl[0], bl[1], bl[2], bl[3], bLo0 + ko);
            ldsm4(bl[4], bl[5], bl[6], bl[7], bLo0 + step16 + ko);
#pragma unroll
            for (int mt = 0; mt < 2; mt++)
#pragma unroll
                for (int nt = 0; nt < 4; nt++) {
                    mma16816(acc[mt][nt], ah[mt], &bh[nt * 2]);
                    mma16816(acc[mt][nt], ah[mt], &bl[nt * 2]);
                    mma16816(acc[mt][nt], al[mt], &bh[nt * 2]);
                }
        }
        __syncthreads();
    }

    // ---- epilogue (validated R11 layouts)
    const int r  = lane >> 2;
    const int cc = (lane & 3) * 2;
#pragma unroll
    for (int mt = 0; mt < 2; mt++) {
        const int mrow = m0 + wm + mt * 16 + r;
        const int b = mrow >> 11;
        const int t = mrow & 2047;
        const int h = n0 >> 6;
#pragma unroll
        for (int nt = 0; nt < 4; nt++) {
            const int ncol = wn + nt * 8 + cc;
            const float a0 = acc[mt][nt][0], a1 = acc[mt][nt][1];
            const float a2 = acc[mt][nt][2], a3 = acc[mt][nt][3];
            if (MODE == 0) {
                float* Y = (float*)Y0;
                *(float2*)&Y[(size_t)mrow * 1024 + n0 + ncol] = make_float2(a0, a1);
                *(float2*)&Y[(size_t)(mrow + 8) * 1024 + n0 + ncol] = make_float2(a2, a3);
            } else if (MODE == 1) {
                bf16* hi = (bf16*)Y0; bf16* lo = (bf16*)Y1;
                const size_t base = ((size_t)((b * H_ + h) * T_ + t)) * DH_ + ncol;
                u32 h01, l01, h23, l23;
                split2(a0, a1, h01, l01);
                split2(a2, a3, h23, l23);
                *(u32*)&hi[base] = h01;
                *(u32*)&lo[base] = l01;
                *(u32*)&hi[base + 8 * DH_] = h23;
                *(u32*)&lo[base + 8 * DH_] = l23;
            } else {
                bf16* hi = (bf16*)Y0; bf16* lo = (bf16*)Y1;
                const size_t r0b = ((size_t)((b * H_ + h) * DH_ + ncol)) * T_;
                const size_t r1b = r0b + T_;
                const float f[4] = {a0, a1, a2, a3};
                const size_t ix[4] = {r0b + t, r1b + t, r0b + t + 8, r1b + t + 8};
#pragma unroll
                for (int e = 0; e < 4; e++) {
                    const bf16 hv = __float2bfloat16(f[e]);
                    hi[ix[e]] = hv;
                    lo[ix[e]] = __float2bfloat16(f[e] - __bfloat162float(hv));
                }
            }
        }
    }
}

// ---------------------------------------------------------------------------
// Pipelined HMMA flash attention: 2-stage cp.async K/V ring.
// CTA = (bh, 128 q-rows), 8 warps x 16 q-rows; 3-product bf16 split.
// ---------------------------------------------------------------------------
#define QSTR 72
#define VSTR 136
#define AQHI 0
#define AQLO 18432
#define ASTG 36864          // stage ring base
#define SK_HI 0
#define SK_LO 18432
#define SV_HI 36864
#define SV_LO 54272
#define ASTG_SZ 71680
#define ATT_SMEM (ASTG + 2 * ASTG_SZ)   // 180224

__global__ __launch_bounds__(256, 1) void attn_hmma(
    const bf16* __restrict__ Qhi, const bf16* __restrict__ Qlo,
    const bf16* __restrict__ Khi, const bf16* __restrict__ Klo,
    const bf16* __restrict__ VThi, const bf16* __restrict__ VTlo,
    bf16* __restrict__ Ohi, bf16* __restrict__ Olo) {
    extern __shared__ __align__(16) char smc[];
    const u32 sb = smem_u32(smc);

    const int qb = gridDim.x - 1 - blockIdx.x;
    const int bh = blockIdx.y;
    const int tid  = threadIdx.x;
    const int wid  = tid >> 5;
    const int lane = tid & 31;
    const int wq = wid * 16;

    const bf16* Kg0 = Khi + (size_t)bh * T_ * DH_;
    const bf16* Kg1 = Klo + (size_t)bh * T_ * DH_;
    const bf16* Vg0 = VThi + (size_t)bh * DH_ * T_;
    const bf16* Vg1 = VTlo + (size_t)bh * DH_ * T_;

    auto stage_kv = [&](int kb, int s) {
        const u32 st = sb + ASTG + (u32)(s * ASTG_SZ);
#pragma unroll
        for (int it = 0; it < 4; it++) {
            const int c = tid + it * 256;
            {   // K tile: 128 rows x 64 bf16 (8 chunks/row)
                const int row = c >> 3, c16 = (c & 7) * 8;
                const size_t gi = (size_t)(kb * 128 + row) * DH_ + c16;
                const u32 so = (u32)((row * QSTR + c16) * 2);
                cpasync16(st + SK_HI + so, Kg0 + gi);
                cpasync16(st + SK_LO + so, Kg1 + gi);
            }
            {   // VT tile: 64 rows x 128 bf16 (16 chunks/row)
                const int row = c >> 4, c16 = (c & 15) * 8;
                const size_t gi = (size_t)row * T_ + kb * 128 + c16;
                const u32 so = (u32)((row * VSTR + c16) * 2);
                cpasync16(st + SV_HI + so, Vg0 + gi);
                cpasync16(st + SV_LO + so, Vg1 + gi);
            }
        }
    };

    // ---- stage Q (regular stores) + start K/V prefetch for kb=0
    const bf16* Qg0 = Qhi + ((size_t)bh * T_ + qb * 128) * DH_;
    const bf16* Qg1 = Qlo + ((size_t)bh * T_ + qb * 128) * DH_;
#pragma unroll
    for (int it = 0; it < 4; it++) {
        const int c = tid + it * 256;
        const int row = c >> 3;
        const int k8  = (c & 7) * 8;
        *(uint4*)(smc + AQHI + (row * QSTR + k8) * 2) = *(const uint4*)&Qg0[row * 64 + k8];
        *(uint4*)(smc + AQLO + (row * QSTR + k8) * 2) = *(const uint4*)&Qg1[row * 64 + k8];
    }
    stage_kv(0, 0); CP_COMMIT();
    __syncthreads();

    // ---- Q fragments resident in registers (overlaps the kb=0 prefetch)
    const int aRow = lane & 15;
    const int aK   = (lane >> 4) * 8;
    const u32 qa = sb + AQHI + ((wq + aRow) * QSTR + aK) * 2;
    u32 qf[2][4][4];
#pragma unroll
    for (int ks = 0; ks < 4; ks++) {
        ldsm4(qf[0][ks][0], qf[0][ks][1], qf[0][ks][2], qf[0][ks][3], qa + ks * 32);
        ldsm4(qf[1][ks][0], qf[1][ks][1], qf[1][ks][2], qf[1][ks][3],
              qa + (AQLO - AQHI) + ks * 32);
    }

    float oacc[8][4];
#pragma unroll
    for (int nt = 0; nt < 8; nt++)
#pragma unroll
        for (int r = 0; r < 4; r++) oacc[nt][r] = 0.f;
    float mrw[2] = {-1e30f, -1e30f}, lrw[2] = {0.f, 0.f};

    const int bN = ((lane >> 4) << 3) | (lane & 7);
    const int bK = ((lane >> 3) & 1) * 8;
    const u32 kOff = (u32)((bN * QSTR + bK) * 2);
    const u32 vOff = (u32)((bN * VSTR + bK) * 2);
    const int r0 = lane >> 2;
    const int cb = (lane & 3) * 2;

    for (int kb = 0; kb <= qb; kb++) {
        // prefetch next tile into the other stage (slot safe: trailing sync of
        // previous iteration orders all lds-reads before these writes)
        if (kb + 1 <= qb) stage_kv(kb + 1, (kb + 1) & 1);
        CP_COMMIT();
        CP_WAIT(1);
        __syncthreads();

        const u32 st = sb + ASTG + (u32)((kb & 1) * ASTG_SZ);
        const u32 kba = st + SK_HI + kOff;
        const u32 vba = st + SV_HI + vOff;

        // ---- S = Q @ K^T (3-product split)
        float sacc[16][4];
#pragma unroll
        for (int nt = 0; nt < 16; nt++)
#pragma unroll
            for (int r = 0; r < 4; r++) sacc[nt][r] = 0.f;

#pragma unroll
        for (int nc = 0; nc < 8; nc++) {
            const u32 nco = (u32)(nc * 16 * QSTR * 2);
#pragma unroll
            for (int ks = 0; ks < 4; ks++) {
                u32 kh[4], kl[4];
                ldsm4(kh[0], kh[1], kh[2], kh[3], kba + nco + ks * 32);
                ldsm4(kl[0], kl[1], kl[2], kl[3],
                      kba + (SK_LO - SK_HI) + nco + ks * 32);
                mma16816(sacc[2 * nc],     qf[0][ks], &kh[0]);
                mma16816(sacc[2 * nc],     qf[0][ks], &kl[0]);
                mma16816(sacc[2 * nc],     qf[1][ks], &kh[0]);
                mma16816(sacc[2 * nc + 1], qf[0][ks], &kh[2]);
                mma16816(sacc[2 * nc + 1], qf[0][ks], &kl[2]);
                mma16816(sacc[2 * nc + 1], qf[1][ks], &kh[2]);
            }
        }

        // ---- scale + mask + online softmax
        const bool diag = (kb == qb);
        float alpha[2];
#pragma unroll
        for (int rh = 0; rh < 2; rh++) {
            const int rl = wq + r0 + rh * 8;
            float mx = -1e30f;
#pragma unroll
            for (int nt = 0; nt < 16; nt++) {
                float v0 = sacc[nt][2 * rh]     * 0.125f;
                float v1 = sacc[nt][2 * rh + 1] * 0.125f;
                if (diag) {
                    const int col = nt * 8 + cb;
                    if (col > rl)     v0 = -1e30f;
                    if (col + 1 > rl) v1 = -1e30f;
                }
                sacc[nt][2 * rh]     = v0;
                sacc[nt][2 * rh + 1] = v1;
                mx = fmaxf(mx, fmaxf(v0, v1));
            }
            mx = fmaxf(mx, __shfl_xor_sync(0xffffffffu, mx, 1));
            mx = fmaxf(mx, __shfl_xor_sync(0xffffffffu, mx, 2));
            const float mnew = fmaxf(mrw[rh], mx);
            alpha[rh] = __expf(mrw[rh] - mnew);
            float rs = 0.f;
#pragma unroll
            for (int nt = 0; nt < 16; nt++) {
                const float p0 = __expf(sacc[nt][2 * rh]     - mnew);
                const float p1 = __expf(sacc[nt][2 * rh + 1] - mnew);
                sacc[nt][2 * rh]     = p0;
                sacc[nt][2 * rh + 1] = p1;
                rs += p0 + p1;
            }
            rs += __shfl_xor_sync(0xffffffffu, rs, 1);
            rs += __shfl_xor_sync(0xffffffffu, rs, 2);
            lrw[rh] = lrw[rh] * alpha[rh] + rs;
            mrw[rh] = mnew;
        }
#pragma unroll
        for (int nt = 0; nt < 8; nt++) {
            oacc[nt][0] *= alpha[0];
            oacc[nt][1] *= alpha[0];
            oacc[nt][2] *= alpha[1];
            oacc[nt][3] *= alpha[1];
        }

        // ---- O += P @ V (register P fragments, 3-product split)
#pragma unroll
        for (int ks = 0; ks < 8; ks++) {
            u32 ph[4], pl[4];
            split2(sacc[2 * ks][0],     sacc[2 * ks][1],     ph[0], pl[0]);
            split2(sacc[2 * ks][2],     sacc[2 * ks][3],     ph[1], pl[1]);
            split2(sacc[2 * ks + 1][0], sacc[2 * ks + 1][1], ph[2], pl[2]);
            split2(sacc[2 * ks + 1][2], sacc[2 * ks + 1][3], ph[3], pl[3]);
#pragma unroll
            for (int nc = 0; nc < 4; nc++) {
                const u32 nco = (u32)(nc * 16 * VSTR * 2);
                u32 vh[4], vl[4];
                ldsm4(vh[0], vh[1], vh[2], vh[3], vba + nco + ks * 32);
                ldsm4(vl[0], vl[1], vl[2], vl[3],
                      vba + (SV_LO - SV_HI) + nco + ks * 32);
                mma16816(oacc[2 * nc],     ph, &vh[0]);
                mma16816(oacc[2 * nc],     ph, &vl[0]);
                mma16816(oacc[2 * nc],     pl, &vh[0]);
                mma16816(oacc[2 * nc + 1], ph, &vh[2]);
                mma16816(oacc[2 * nc + 1], ph, &vl[2]);
                mma16816(oacc[2 * nc + 1], pl, &vh[2]);
            }
        }
        __syncthreads();   // all reads of this stage done before next prefetch
    }

    // ---- normalize + bf16 hi/lo write to (B,T,D)
    const float inv0 = 1.f / lrw[0];
    const float inv1 = 1.f / lrw[1];
    const int b  = bh >> 4;
    const int hh = bh & 15;
    const int t0 = qb * 128 + wq + r0;
#pragma unroll
    for (int nt = 0; nt < 8; nt++) {
        const int col = hh * 64 + nt * 8 + cb;
        u32 h01, l01, h23, l23;
        split2(oacc[nt][0] * inv0, oacc[nt][1] * inv0, h01, l01);
        split2(oacc[nt][2] * inv1, oacc[nt][3] * inv1, h23, l23);
        const size_t i0 = ((size_t)(b * T_ + t0)) * D_ + col;
        const size_t i1 = ((size_t)(b * T_ + t0 + 8)) * D_ + col;
        *(u32*)&Ohi[i0] = h01;
        *(u32*)&Olo[i0] = l01;
        *(u32*)&Ohi[i1] = h23;
        *(u32*)&Olo[i1] = l23;
    }
}

// ---------------------------------------------------------------------------
// Host launcher (graph-capturable)
// ---------------------------------------------------------------------------
extern "C" void kernel_launch(void* const* d_in, const int* in_sizes, int n_in,
                              void* d_out, int out_size) {
    (void)in_sizes; (void)n_in; (void)out_size;
    const float* x = (const float*)d_in[0];
    const float* W[4] = {(const float*)d_in[1], (const float*)d_in[2],
                         (const float*)d_in[3], (const float*)d_in[4]};
    float* out = (float*)d_out;

    bf16 *xhi, *xlo, *wT, *qhi, *qlo, *khi, *klo, *vthi, *vtlo, *ahi, *alo;
    cudaGetSymbolAddress((void**)&xhi,  g_xhi);
    cudaGetSymbolAddress((void**)&xlo,  g_xlo);
    cudaGetSymbolAddress((void**)&wT,   g_wT);
    cudaGetSymbolAddress((void**)&qhi,  g_qhi);
    cudaGetSymbolAddress((void**)&qlo,  g_qlo);
    cudaGetSymbolAddress((void**)&khi,  g_khi);
    cudaGetSymbolAddress((void**)&klo,  g_klo);
    cudaGetSymbolAddress((void**)&vthi, g_vthi);
    cudaGetSymbolAddress((void**)&vtlo, g_vtlo);
    cudaGetSymbolAddress((void**)&ahi,  g_ahi);
    cudaGetSymbolAddress((void**)&alo,  g_alo);

    cudaFuncSetAttribute(hmma_gemm<0>, cudaFuncAttributeMaxDynamicSharedMemorySize, GS_TOT);
    cudaFuncSetAttribute(hmma_gemm<1>, cudaFuncAttributeMaxDynamicSharedMemorySize, GS_TOT);
    cudaFuncSetAttribute(hmma_gemm<2>, cudaFuncAttributeMaxDynamicSharedMemorySize, GS_TOT);
    cudaFuncSetAttribute(attn_hmma, cudaFuncAttributeMaxDynamicSharedMemorySize, ATT_SMEM);

    // --- pre-pass ---
    split_kernel<<<M_ * D_ / 1024, 256>>>(x, xhi, xlo);
    const dim3 tgrid(D_ / 32, D_ / 32);
    for (int w = 0; w < 4; w++)
        tsplit_kernel<<<tgrid, 256>>>(W[w],
                                      wT + (size_t)(2 * w)     * D_ * D_,
                                      wT + (size_t)(2 * w + 1) * D_ * D_);

    // --- projections ---
    const dim3 ggrid(D_ / 64, M_ / 128);
    hmma_gemm<1><<<ggrid, 256, GS_TOT>>>(xhi, xlo,
        wT + 0 * (size_t)D_ * D_, wT + 1 * (size_t)D_ * D_, qhi, qlo);
    hmma_gemm<1><<<ggrid, 256, GS_TOT>>>(xhi, xlo,
        wT + 2 * (size_t)D_ * D_, wT + 3 * (size_t)D_ * D_, khi, klo);
    hmma_gemm<2><<<ggrid, 256, GS_TOT>>>(xhi, xlo,
        wT + 4 * (size_t)D_ * D_, wT + 5 * (size_t)D_ * D_, vthi, vtlo);

    // --- attention ---
    const dim3 agrid(T_ / 128, BH_);
    attn_hmma<<<agrid, 256, ATT_SMEM>>>(qhi, qlo, khi, klo, vthi, vtlo, ahi, alo);

    // --- output projection ---
    hmma_gemm<0><<<ggrid, 256, GS_TOT>>>(ahi, alo,
        wT + 6 * (size_t)D_ * D_, wT + 7 * (size_t)D_ * D_, out, nullptr);
}

// round 14
// speedup vs baseline: 1.0738x; 1.0738x over previous
#include <cuda_runtime.h>
#include <cuda_bf16.h>
#include <cstdint>
#include <math.h>

#define B_  2
#define T_  2048
#define D_  1024
#define H_  16
#define DH_ 64
#define M_  (B_ * T_)
#define BH_ (B_ * H_)

typedef unsigned long long u64;
typedef unsigned int u32;
typedef __nv_bfloat16 bf16;

// ---------------------------------------------------------------------------
// Generic tensor-core + cp.async PTX (sm_80+, legal under compute_103)
// ---------------------------------------------------------------------------
__device__ __forceinline__ u32 smem_u32(const void* p) {
    u32 a;
    asm("{ .reg .u64 t; cvta.to.shared.u64 t, %1; cvt.u32.u64 %0, t; }"
        : "=r"(a) : "l"(p));
    return a;
}
__device__ __forceinline__ void ldsm4(u32& r0, u32& r1, u32& r2, u32& r3, u32 addr) {
    asm volatile("ldmatrix.sync.aligned.m8n8.x4.shared.b16 {%0,%1,%2,%3}, [%4];"
                 : "=r"(r0), "=r"(r1), "=r"(r2), "=r"(r3) : "r"(addr));
}
__device__ __forceinline__ void mma16816(float* c, const u32* a, const u32* b) {
    asm volatile("mma.sync.aligned.m16n8k16.row.col.f32.bf16.bf16.f32 "
                 "{%0,%1,%2,%3}, {%4,%5,%6,%7}, {%8,%9}, {%0,%1,%2,%3};"
                 : "+f"(c[0]), "+f"(c[1]), "+f"(c[2]), "+f"(c[3])
                 : "r"(a[0]), "r"(a[1]), "r"(a[2]), "r"(a[3]),
                   "r"(b[0]), "r"(b[1]));
}
__device__ __forceinline__ void cpasync16(u32 s, const void* g) {
    asm volatile("cp.async.cg.shared.global [%0], [%1], 16;" :: "r"(s), "l"(g));
}
#define CP_COMMIT()  asm volatile("cp.async.commit_group;" ::: "memory")
#define CP_WAIT(n)   asm volatile("cp.async.wait_group " #n ";" ::: "memory")

__device__ __forceinline__ void split2(float a, float b, u32& hi, u32& lo) {
    __nv_bfloat162 h = __float22bfloat162_rn(make_float2(a, b));
    float2 hf = __bfloat1622float2(h);
    __nv_bfloat162 l = __float22bfloat162_rn(make_float2(a - hf.x, b - hf.y));
    hi = *(u32*)&h;
    lo = *(u32*)&l;
}

// ---------------------------------------------------------------------------
// Scratch
// ---------------------------------------------------------------------------
__device__ __align__(16) bf16 g_xhi[M_ * D_];
__device__ __align__(16) bf16 g_xlo[M_ * D_];
__device__ __align__(16) bf16 g_wT[4 * 2 * D_ * D_];        // [w][hi/lo][N][K]
__device__ __align__(16) bf16 g_qhi[BH_ * T_ * DH_];        // pre-scaled by 0.125
__device__ __align__(16) bf16 g_qlo[BH_ * T_ * DH_];
__device__ __align__(16) bf16 g_khi[BH_ * T_ * DH_];
__device__ __align__(16) bf16 g_klo[BH_ * T_ * DH_];
__device__ __align__(16) bf16 g_vthi[BH_ * DH_ * T_];       // V^T (B,H,DH,T)
__device__ __align__(16) bf16 g_vtlo[BH_ * DH_ * T_];
__device__ __align__(16) bf16 g_ahi[M_ * D_];
__device__ __align__(16) bf16 g_alo[M_ * D_];

// ---------------------------------------------------------------------------
// Pre-pass kernels (validated)
// ---------------------------------------------------------------------------
__global__ __launch_bounds__(256) void split_kernel(const float* __restrict__ src,
                                                    bf16* __restrict__ hi,
                                                    bf16* __restrict__ lo) {
    const int i = (blockIdx.x * 256 + threadIdx.x) * 4;
    const float4 v = *(const float4*)&src[i];
    bf16 h[4], l[4];
    const float f[4] = {v.x, v.y, v.z, v.w};
#pragma unroll
    for (int j = 0; j < 4; j++) {
        h[j] = __float2bfloat16(f[j]);
        l[j] = __float2bfloat16(f[j] - __bfloat162float(h[j]));
    }
    *(uint2*)&hi[i] = *(const uint2*)h;
    *(uint2*)&lo[i] = *(const uint2*)l;
}

__global__ __launch_bounds__(256) void tsplit_kernel(const float* __restrict__ W,
                                                     bf16* __restrict__ hiT,
                                                     bf16* __restrict__ loT) {
    __shared__ float t[32][33];
    const int tx = threadIdx.x & 31;
    const int ty = threadIdx.x >> 5;
    const int bn = blockIdx.x * 32;
    const int bk = blockIdx.y * 32;
#pragma unroll
    for (int i = 0; i < 4; i++)
        t[ty + 8 * i][tx] = W[(size_t)(bk + ty + 8 * i) * D_ + bn + tx];
    __syncthreads();
#pragma unroll
    for (int i = 0; i < 4; i++) {
        const int n = bn + ty + 8 * i;
        const float v = t[tx][ty + 8 * i];
        const bf16 h = __float2bfloat16(v);
        const bf16 l = __float2bfloat16(v - __bfloat162float(h));
        hiT[(size_t)n * D_ + bk + tx] = h;
        loT[(size_t)n * D_ + bk + tx] = l;
    }
}

// ---------------------------------------------------------------------------
// HMMA GEMM: BM=128, BN=64, BK=64, 2-stage cp.async, NO reg clamp.
// Layout/inner loop identical to validated R11 (KSTR=72).
// MODE 0: f32 row-major. MODE 1: bf16 hi/lo (B,H,T,DH) scaled by oscale.
// MODE 2: bf16 hi/lo V^T.
// ---------------------------------------------------------------------------
#define KSTR 72
#define STG_AHI 0
#define STG_ALO 18432
#define STG_WHI 36864
#define STG_WLO 46080
#define STG_SZ  55296
#define NTILE   16
#define GS_TOT  (2 * STG_SZ)   // 110592

template <int MODE>
__global__ __launch_bounds__(256) void hmma_gemm(
    const bf16* __restrict__ Ahi, const bf16* __restrict__ Alo,
    const bf16* __restrict__ WhiT, const bf16* __restrict__ WloT,
    void* __restrict__ Y0, void* __restrict__ Y1, float oscale) {
    extern __shared__ __align__(16) char gsm[];
    const u32 sbase = smem_u32(gsm);

    const int tid  = threadIdx.x;
    const int wid  = tid >> 5;
    const int lane = tid & 31;
    const int m0 = blockIdx.y * 128;
    const int n0 = blockIdx.x * 64;
    const int wm = (wid >> 1) * 32;
    const int wn = (wid & 1) * 32;

    auto load_tile = [&](int kt, int s) {
        const u32 sb = sbase + (u32)(s * STG_SZ);
        const int kb = kt * 64;
#pragma unroll
        for (int it = 0; it < 4; it++) {
            const int c = tid + it * 256;
            const int row = c >> 3;
            const int c8  = (c & 7) * 8;
            const u32 so = (u32)((row * KSTR + c8) * 2);
            const size_t gi = (size_t)(m0 + row) * D_ + kb + c8;
            cpasync16(sb + STG_AHI + so, Ahi + gi);
            cpasync16(sb + STG_ALO + so, Alo + gi);
        }
#pragma unroll
        for (int it = 0; it < 2; it++) {
            const int c = tid + it * 256;
            const int row = c >> 3;
            const int c8  = (c & 7) * 8;
            const u32 so = (u32)((row * KSTR + c8) * 2);
            const size_t gi = (size_t)(n0 + row) * D_ + kb + c8;
            cpasync16(sb + STG_WHI + so, WhiT + gi);
            cpasync16(sb + STG_WLO + so, WloT + gi);
        }
    };

    // ldmatrix per-lane offsets (validated)
    const int aRow = lane & 15;
    const int aK   = (lane >> 4) * 8;
    const int bN   = ((lane >> 4) << 3) | (lane & 7);
    const int bK   = ((lane >> 3) & 1) * 8;
    const u32 aOff = (u32)(((wm + aRow) * KSTR + aK) * 2);
    const u32 bOff = (u32)(((wn + bN) * KSTR + bK) * 2);
    const u32 step16 = 16 * KSTR * 2;

    float acc[2][4][4];
#pragma unroll
    for (int mt = 0; mt < 2; mt++)
#pragma unroll
        for (int nt = 0; nt < 4; nt++)
#pragma unroll
            for (int r = 0; r < 4; r++) acc[mt][nt][r] = 0.f;

    load_tile(0, 0);
    CP_COMMIT();

    for (int kt = 0; kt < NTILE; kt++) {
        if (kt + 1 < NTILE) load_tile(kt + 1, (kt + 1) & 1);
        CP_COMMIT();
        CP_WAIT(1);          // tile kt resident (kt+1's group may remain in flight)
        __syncthreads();

        const u32 sb = sbase + (u32)((kt & 1) * STG_SZ);
        const u32 aHi0 = sb + STG_AHI + aOff;
        const u32 aLo0 = sb + STG_ALO + aOff;
        const u32 bHi0 = sb + STG_WHI + bOff;
        const u32 bLo0 = sb + STG_WLO + bOff;
#pragma unroll
        for (int ks = 0; ks < 4; ks++) {
            const u32 ko = ks * 32;
            u32 ah[2][4], al[2][4], bh[8], bl[8];
            ldsm4(ah[0][0], ah[0][1], ah[0][2], ah[0][3], aHi0 + ko);
            ldsm4(ah[1][0], ah[1][1], ah[1][2], ah[1][3], aHi0 + step16 + ko);
            ldsm4(al[0][0], al[0][1], al[0][2], al[0][3], aLo0 + ko);
            ldsm4(al[1][0], al[1][1], al[1][2], al[1][3], aLo0 + step16 + ko);
            ldsm4(bh[0], bh[1], bh[2], bh[3], bHi0 + ko);
            ldsm4(bh[4], bh[5], bh[6], bh[7], bHi0 + step16 + ko);
            ldsm4(bl[0], bl[1], bl[2], bl[3], bLo0 + ko);
            ldsm4(bl[4], bl[5], bl[6], bl[7], bLo0 + step16 + ko);
#pragma unroll
            for (int mt = 0; mt < 2; mt++)
#pragma unroll
                for (int nt = 0; nt < 4; nt++) {
                    mma16816(acc[mt][nt], ah[mt], &bh[nt * 2]);
                    mma16816(acc[mt][nt], ah[mt], &bl[nt * 2]);
                    mma16816(acc[mt][nt], al[mt], &bh[nt * 2]);
                }
        }
        __syncthreads();     // stage reads done before next overwrite
    }

    // ---- epilogue (validated layouts)
    const int r  = lane >> 2;
    const int cc = (lane & 3) * 2;
#pragma unroll
    for (int mt = 0; mt < 2; mt++) {
        const int mrow = m0 + wm + mt * 16 + r;
        const int b = mrow >> 11;
        const int t = mrow & 2047;
        const int h = n0 >> 6;
#pragma unroll
        for (int nt = 0; nt < 4; nt++) {
            const int ncol = wn + nt * 8 + cc;
            const float a0 = acc[mt][nt][0] * oscale, a1 = acc[mt][nt][1] * oscale;
            const float a2 = acc[mt][nt][2] * oscale, a3 = acc[mt][nt][3] * oscale;
            if (MODE == 0) {
                float* Y = (float*)Y0;
                *(float2*)&Y[(size_t)mrow * 1024 + n0 + ncol] = make_float2(a0, a1);
                *(float2*)&Y[(size_t)(mrow + 8) * 1024 + n0 + ncol] = make_float2(a2, a3);
            } else if (MODE == 1) {
                bf16* hi = (bf16*)Y0; bf16* lo = (bf16*)Y1;
                const size_t base = ((size_t)((b * H_ + h) * T_ + t)) * DH_ + ncol;
                u32 h01, l01, h23, l23;
                split2(a0, a1, h01, l01);
                split2(a2, a3, h23, l23);
                *(u32*)&hi[base] = h01;
                *(u32*)&lo[base] = l01;
                *(u32*)&hi[base + 8 * DH_] = h23;
                *(u32*)&lo[base + 8 * DH_] = l23;
            } else {
                bf16* hi = (bf16*)Y0; bf16* lo = (bf16*)Y1;
                const size_t r0b = ((size_t)((b * H_ + h) * DH_ + ncol)) * T_;
                const size_t r1b = r0b + T_;
                const float f[4] = {a0, a1, a2, a3};
                const size_t ix[4] = {r0b + t, r1b + t, r0b + t + 8, r1b + t + 8};
#pragma unroll
                for (int e = 0; e < 4; e++) {
                    const bf16 hv = __float2bfloat16(f[e]);
                    hi[ix[e]] = hv;
                    lo[ix[e]] = __float2bfloat16(f[e] - __bfloat162float(hv));
                }
            }
        }
    }
}

// ---------------------------------------------------------------------------
// Pipelined HMMA flash attention (R12 structure, validated correct).
// Q arrives pre-scaled by 1/sqrt(DH) -> no scale in softmax.
// ---------------------------------------------------------------------------
#define QSTR 72
#define VSTR 136
#define AQHI 0
#define AQLO 18432
#define ASTG 36864
#define SK_HI 0
#define SK_LO 18432
#define SV_HI 36864
#define SV_LO 54272
#define ASTG_SZ 71680
#define ATT_SMEM (ASTG + 2 * ASTG_SZ)   // 180224

__global__ __launch_bounds__(256, 1) void attn_hmma(
    const bf16* __restrict__ Qhi, const bf16* __restrict__ Qlo,
    const bf16* __restrict__ Khi, const bf16* __restrict__ Klo,
    const bf16* __restrict__ VThi, const bf16* __restrict__ VTlo,
    bf16* __restrict__ Ohi, bf16* __restrict__ Olo) {
    extern __shared__ __align__(16) char smc[];
    const u32 sb = smem_u32(smc);

    const int qb = gridDim.x - 1 - blockIdx.x;
    const int bh = blockIdx.y;
    const int tid  = threadIdx.x;
    const int wid  = tid >> 5;
    const int lane = tid & 31;
    const int wq = wid * 16;

    const bf16* Kg0 = Khi + (size_t)bh * T_ * DH_;
    const bf16* Kg1 = Klo + (size_t)bh * T_ * DH_;
    const bf16* Vg0 = VThi + (size_t)bh * DH_ * T_;
    const bf16* Vg1 = VTlo + (size_t)bh * DH_ * T_;

    auto stage_kv = [&](int kb, int s) {
        const u32 st = sb + ASTG + (u32)(s * ASTG_SZ);
#pragma unroll
        for (int it = 0; it < 4; it++) {
            const int c = tid + it * 256;
            {
                const int row = c >> 3, c16 = (c & 7) * 8;
                const size_t gi = (size_t)(kb * 128 + row) * DH_ + c16;
                const u32 so = (u32)((row * QSTR + c16) * 2);
                cpasync16(st + SK_HI + so, Kg0 + gi);
                cpasync16(st + SK_LO + so, Kg1 + gi);
            }
            {
                const int row = c >> 4, c16 = (c & 15) * 8;
                const size_t gi = (size_t)row * T_ + kb * 128 + c16;
                const u32 so = (u32)((row * VSTR + c16) * 2);
                cpasync16(st + SV_HI + so, Vg0 + gi);
                cpasync16(st + SV_LO + so, Vg1 + gi);
            }
        }
    };

    const bf16* Qg0 = Qhi + ((size_t)bh * T_ + qb * 128) * DH_;
    const bf16* Qg1 = Qlo + ((size_t)bh * T_ + qb * 128) * DH_;
#pragma unroll
    for (int it = 0; it < 4; it++) {
        const int c = tid + it * 256;
        const int row = c >> 3;
        const int k8  = (c & 7) * 8;
        *(uint4*)(smc + AQHI + (row * QSTR + k8) * 2) = *(const uint4*)&Qg0[row * 64 + k8];
        *(uint4*)(smc + AQLO + (row * QSTR + k8) * 2) = *(const uint4*)&Qg1[row * 64 + k8];
    }
    stage_kv(0, 0); CP_COMMIT();
    __syncthreads();

    const int aRow = lane & 15;
    const int aK   = (lane >> 4) * 8;
    const u32 qa = sb + AQHI + ((wq + aRow) * QSTR + aK) * 2;
    u32 qf[2][4][4];
#pragma unroll
    for (int ks = 0; ks < 4; ks++) {
        ldsm4(qf[0][ks][0], qf[0][ks][1], qf[0][ks][2], qf[0][ks][3], qa + ks * 32);
        ldsm4(qf[1][ks][0], qf[1][ks][1], qf[1][ks][2], qf[1][ks][3],
              qa + (AQLO - AQHI) + ks * 32);
    }

    float oacc[8][4];
#pragma unroll
    for (int nt = 0; nt < 8; nt++)
#pragma unroll
        for (int r = 0; r < 4; r++) oacc[nt][r] = 0.f;
    float mrw[2] = {-1e30f, -1e30f}, lrw[2] = {0.f, 0.f};

    const int bN = ((lane >> 4) << 3) | (lane & 7);
    const int bK = ((lane >> 3) & 1) * 8;
    const u32 kOff = (u32)((bN * QSTR + bK) * 2);
    const u32 vOff = (u32)((bN * VSTR + bK) * 2);
    const int r0 = lane >> 2;
    const int cb = (lane & 3) * 2;

    for (int kb = 0; kb <= qb; kb++) {
        if (kb + 1 <= qb) stage_kv(kb + 1, (kb + 1) & 1);
        CP_COMMIT();
        CP_WAIT(1);
        __syncthreads();

        const u32 st = sb + ASTG + (u32)((kb & 1) * ASTG_SZ);
        const u32 kba = st + SK_HI + kOff;
        const u32 vba = st + SV_HI + vOff;

        float sacc[16][4];
#pragma unroll
        for (int nt = 0; nt < 16; nt++)
#pragma unroll
            for (int r = 0; r < 4; r++) sacc[nt][r] = 0.f;

#pragma unroll
        for (int nc = 0; nc < 8; nc++) {
            const u32 nco = (u32)(nc * 16 * QSTR * 2);
#pragma unroll
            for (int ks = 0; ks < 4; ks++) {
                u32 kh[4], kl[4];
                ldsm4(kh[0], kh[1], kh[2], kh[3], kba + nco + ks * 32);
                ldsm4(kl[0], kl[1], kl[2], kl[3],
                      kba + (SK_LO - SK_HI) + nco + ks * 32);
                mma16816(sacc[2 * nc],     qf[0][ks], &kh[0]);
                mma16816(sacc[2 * nc],     qf[0][ks], &kl[0]);
                mma16816(sacc[2 * nc],     qf[1][ks], &kh[0]);
                mma16816(sacc[2 * nc + 1], qf[0][ks], &kh[2]);
                mma16816(sacc[2 * nc + 1], qf[0][ks], &kl[2]);
                mma16816(sacc[2 * nc + 1], qf[1][ks], &kh[2]);
            }
        }

        const bool diag = (kb == qb);
        float alpha[2];
#pragma unroll
        for (int rh = 0; rh < 2; rh++) {
            const int rl = wq + r0 + rh * 8;
            float mx = -1e30f;
#pragma unroll
            for (int nt = 0; nt < 16; nt++) {
                float v0 = sacc[nt][2 * rh];          // Q pre-scaled: no 0.125 here
                float v1 = sacc[nt][2 * rh + 1];
                if (diag) {
                    const int col = nt * 8 + cb;
                    if (col > rl)     v0 = -1e30f;
                    if (col + 1 > rl) v1 = -1e30f;
                }
                sacc[nt][2 * rh]     = v0;
                sacc[nt][2 * rh + 1] = v1;
                mx = fmaxf(mx, fmaxf(v0, v1));
            }
            mx = fmaxf(mx, __shfl_xor_sync(0xffffffffu, mx, 1));
            mx = fmaxf(mx, __shfl_xor_sync(0xffffffffu, mx, 2));
            const float mnew = fmaxf(mrw[rh], mx);
            alpha[rh] = __expf(mrw[rh] - mnew);
            float rs = 0.f;
#pragma unroll
            for (int nt = 0; nt < 16; nt++) {
                const float p0 = __expf(sacc[nt][2 * rh]     - mnew);
                const float p1 = __expf(sacc[nt][2 * rh + 1] - mnew);
                sacc[nt][2 * rh]     = p0;
                sacc[nt][2 * rh + 1] = p1;
                rs += p0 + p1;
            }
            rs += __shfl_xor_sync(0xffffffffu, rs, 1);
            rs += __shfl_xor_sync(0xffffffffu, rs, 2);
            lrw[rh] = lrw[rh] * alpha[rh] + rs;
            mrw[rh] = mnew;
        }
#pragma unroll
        for (int nt = 0; nt < 8; nt++) {
            oacc[nt][0] *= alpha[0];
            oacc[nt][1] *= alpha[0];
            oacc[nt][2] *= alpha[1];
            oacc[nt][3] *= alpha[1];
        }

#pragma unroll
        for (int ks = 0; ks < 8; ks++) {
            u32 ph[4], pl[4];
            split2(sacc[2 * ks][0],     sacc[2 * ks][1],     ph[0], pl[0]);
            split2(sacc[2 * ks][2],     sacc[2 * ks][3],     ph[1], pl[1]);
            split2(sacc[2 * ks + 1][0], sacc[2 * ks + 1][1], ph[2], pl[2]);
            split2(sacc[2 * ks + 1][2], sacc[2 * ks + 1][3], ph[3], pl[3]);
#pragma unroll
            for (int nc = 0; nc < 4; nc++) {
                const u32 nco = (u32)(nc * 16 * VSTR * 2);
                u32 vh[4], vl[4];
                ldsm4(vh[0], vh[1], vh[2], vh[3], vba + nco + ks * 32);
                ldsm4(vl[0], vl[1], vl[2], vl[3],
                      vba + (SV_LO - SV_HI) + nco + ks * 32);
                mma16816(oacc[2 * nc],     ph, &vh[0]);
                mma16816(oacc[2 * nc],     ph, &vl[0]);
                mma16816(oacc[2 * nc],     pl, &vh[0]);
                mma16816(oacc[2 * nc + 1], ph, &vh[2]);
                mma16816(oacc[2 * nc + 1], ph, &vl[2]);
                mma16816(oacc[2 * nc + 1], pl, &vh[2]);
            }
        }
        __syncthreads();
    }

    const float inv0 = 1.f / lrw[0];
    const float inv1 = 1.f / lrw[1];
    const int b  = bh >> 4;
    const int hh = bh & 15;
    const int t0 = qb * 128 + wq + r0;
#pragma unroll
    for (int nt = 0; nt < 8; nt++) {
        const int col = hh * 64 + nt * 8 + cb;
        u32 h01, l01, h23, l23;
        split2(oacc[nt][0] * inv0, oacc[nt][1] * inv0, h01, l01);
        split2(oacc[nt][2] * inv1, oacc[nt][3] * inv1, h23, l23);
        const size_t i0 = ((size_t)(b * T_ + t0)) * D_ + col;
        const size_t i1 = ((size_t)(b * T_ + t0 + 8)) * D_ + col;
        *(u32*)&Ohi[i0] = h01;
        *(u32*)&Olo[i0] = l01;
        *(u32*)&Ohi[i1] = h23;
        *(u32*)&Olo[i1] = l23;
    }
}

// ---------------------------------------------------------------------------
// Host launcher (graph-capturable)
// ---------------------------------------------------------------------------
extern "C" void kernel_launch(void* const* d_in, const int* in_sizes, int n_in,
                              void* d_out, int out_size) {
    (void)in_sizes; (void)n_in; (void)out_size;
    const float* x = (const float*)d_in[0];
    const float* W[4] = {(const float*)d_in[1], (const float*)d_in[2],
                         (const float*)d_in[3], (const float*)d_in[4]};
    float* out = (float*)d_out;

    bf16 *xhi, *xlo, *wT, *qhi, *qlo, *khi, *klo, *vthi, *vtlo, *ahi, *alo;
    cudaGetSymbolAddress((void**)&xhi,  g_xhi);
    cudaGetSymbolAddress((void**)&xlo,  g_xlo);
    cudaGetSymbolAddress((void**)&wT,   g_wT);
    cudaGetSymbolAddress((void**)&qhi,  g_qhi);
    cudaGetSymbolAddress((void**)&qlo,  g_qlo);
    cudaGetSymbolAddress((void**)&khi,  g_khi);
    cudaGetSymbolAddress((void**)&klo,  g_klo);
    cudaGetSymbolAddress((void**)&vthi, g_vthi);
    cudaGetSymbolAddress((void**)&vtlo, g_vtlo);
    cudaGetSymbolAddress((void**)&ahi,  g_ahi);
    cudaGetSymbolAddress((void**)&alo,  g_alo);

    cudaFuncSetAttribute(hmma_gemm<0>, cudaFuncAttributeMaxDynamicSharedMemorySize, GS_TOT);
    cudaFuncSetAttribute(hmma_gemm<1>, cudaFuncAttributeMaxDynamicSharedMemorySize, GS_TOT);
    cudaFuncSetAttribute(hmma_gemm<2>, cudaFuncAttributeMaxDynamicSharedMemorySize, GS_TOT);
    cudaFuncSetAttribute(attn_hmma, cudaFuncAttributeMaxDynamicSharedMemorySize, ATT_SMEM);

    // --- pre-pass ---
    split_kernel<<<M_ * D_ / 1024, 256>>>(x, xhi, xlo);
    const dim3 tgrid(D_ / 32, D_ / 32);
    for (int w = 0; w < 4; w++)
        tsplit_kernel<<<tgrid, 256>>>(W[w],
                                      wT + (size_t)(2 * w)     * D_ * D_,
                                      wT + (size_t)(2 * w + 1) * D_ * D_);

    // --- projections (Q scaled by 1/sqrt(DH) = 0.125, exact in bf16) ---
    const dim3 ggrid(D_ / 64, M_ / 128);
    hmma_gemm<1><<<ggrid, 256, GS_TOT>>>(xhi, xlo,
        wT + 0 * (size_t)D_ * D_, wT + 1 * (size_t)D_ * D_, qhi, qlo, 0.125f);
    hmma_gemm<1><<<ggrid, 256, GS_TOT>>>(xhi, xlo,
        wT + 2 * (size_t)D_ * D_, wT + 3 * (size_t)D_ * D_, khi, klo, 1.0f);
    hmma_gemm<2><<<ggrid, 256, GS_TOT>>>(xhi, xlo,
        wT + 4 * (size_t)D_ * D_, wT + 5 * (size_t)D_ * D_, vthi, vtlo, 1.0f);

    // --- attention ---
    const dim3 agrid(T_ / 128, BH_);
    attn_hmma<<<agrid, 256, ATT_SMEM>>>(qhi, qlo, khi, klo, vthi, vtlo, ahi, alo);

    // --- output projection ---
    hmma_gemm<0><<<ggrid, 256, GS_TOT>>>(ahi, alo,
        wT + 6 * (size_t)D_ * D_, wT + 7 * (size_t)D_ * D_, out, nullptr, 1.0f);
}

// round 16
// speedup vs baseline: 1.1624x; 1.0825x over previous
#include <cuda_runtime.h>
#include <cuda_bf16.h>
#include <cstdint>
#include <math.h>

#define B_  2
#define T_  2048
#define D_  1024
#define H_  16
#define DH_ 64
#define M_  (B_ * T_)
#define BH_ (B_ * H_)

typedef unsigned long long u64;
typedef unsigned int u32;
typedef __nv_bfloat16 bf16;

// ---------------------------------------------------------------------------
// Generic tensor-core + cp.async PTX (sm_80+, legal under compute_103)
// ---------------------------------------------------------------------------
__device__ __forceinline__ u32 smem_u32(const void* p) {
    u32 a;
    asm("{ .reg .u64 t; cvta.to.shared.u64 t, %1; cvt.u32.u64 %0, t; }"
        : "=r"(a) : "l"(p));
    return a;
}
__device__ __forceinline__ void ldsm4(u32& r0, u32& r1, u32& r2, u32& r3, u32 addr) {
    asm volatile("ldmatrix.sync.aligned.m8n8.x4.shared.b16 {%0,%1,%2,%3}, [%4];"
                 : "=r"(r0), "=r"(r1), "=r"(r2), "=r"(r3) : "r"(addr));
}
__device__ __forceinline__ void mma16816(float* c, const u32* a, const u32* b) {
    asm volatile("mma.sync.aligned.m16n8k16.row.col.f32.bf16.bf16.f32 "
                 "{%0,%1,%2,%3}, {%4,%5,%6,%7}, {%8,%9}, {%0,%1,%2,%3};"
                 : "+f"(c[0]), "+f"(c[1]), "+f"(c[2]), "+f"(c[3])
                 : "r"(a[0]), "r"(a[1]), "r"(a[2]), "r"(a[3]),
                   "r"(b[0]), "r"(b[1]));
}
__device__ __forceinline__ void cpasync16(u32 s, const void* g) {
    asm volatile("cp.async.cg.shared.global [%0], [%1], 16;" :: "r"(s), "l"(g));
}
#define CP_COMMIT()  asm volatile("cp.async.commit_group;" ::: "memory")
#define CP_WAIT(n)   asm volatile("cp.async.wait_group " #n ";" ::: "memory")

__device__ __forceinline__ void split2(float a, float b, u32& hi, u32& lo) {
    __nv_bfloat162 h = __float22bfloat162_rn(make_float2(a, b));
    float2 hf = __bfloat1622float2(h);
    __nv_bfloat162 l = __float22bfloat162_rn(make_float2(a - hf.x, b - hf.y));
    hi = *(u32*)&h;
    lo = *(u32*)&l;
}

// ---------------------------------------------------------------------------
// Scratch
// ---------------------------------------------------------------------------
__device__ __align__(16) bf16 g_xhi[M_ * D_];
__device__ __align__(16) bf16 g_xlo[M_ * D_];
__device__ __align__(16) bf16 g_wT[4 * 2 * D_ * D_];        // [w][hi/lo][N][K]
__device__ __align__(16) bf16 g_qhi[BH_ * T_ * DH_];        // pre-scaled by 0.125
__device__ __align__(16) bf16 g_qlo[BH_ * T_ * DH_];
__device__ __align__(16) bf16 g_khi[BH_ * T_ * DH_];
__device__ __align__(16) bf16 g_klo[BH_ * T_ * DH_];
__device__ __align__(16) bf16 g_vthi[BH_ * DH_ * T_];       // V^T (B,H,DH,T)
__device__ __align__(16) bf16 g_vtlo[BH_ * DH_ * T_];
__device__ __align__(16) bf16 g_ahi[M_ * D_];
__device__ __align__(16) bf16 g_alo[M_ * D_];

// ---------------------------------------------------------------------------
// Pre-pass kernels (validated)
// ---------------------------------------------------------------------------
__global__ __launch_bounds__(256) void split_kernel(const float* __restrict__ src,
                                                    bf16* __restrict__ hi,
                                                    bf16* __restrict__ lo) {
    const int i = (blockIdx.x * 256 + threadIdx.x) * 4;
    const float4 v = *(const float4*)&src[i];
    bf16 h[4], l[4];
    const float f[4] = {v.x, v.y, v.z, v.w};
#pragma unroll
    for (int j = 0; j < 4; j++) {
        h[j] = __float2bfloat16(f[j]);
        l[j] = __float2bfloat16(f[j] - __bfloat162float(h[j]));
    }
    *(uint2*)&hi[i] = *(const uint2*)h;
    *(uint2*)&lo[i] = *(const uint2*)l;
}

__global__ __launch_bounds__(256) void tsplit_kernel(const float* __restrict__ W,
                                                     bf16* __restrict__ hiT,
                                                     bf16* __restrict__ loT) {
    __shared__ float t[32][33];
    const int tx = threadIdx.x & 31;
    const int ty = threadIdx.x >> 5;
    const int bn = blockIdx.x * 32;
    const int bk = blockIdx.y * 32;
#pragma unroll
    for (int i = 0; i < 4; i++)
        t[ty + 8 * i][tx] = W[(size_t)(bk + ty + 8 * i) * D_ + bn + tx];
    __syncthreads();
#pragma unroll
    for (int i = 0; i < 4; i++) {
        const int n = bn + ty + 8 * i;
        const float v = t[tx][ty + 8 * i];
        const bf16 h = __float2bfloat16(v);
        const bf16 l = __float2bfloat16(v - __bfloat162float(h));
        hiT[(size_t)n * D_ + bk + tx] = h;
        loT[(size_t)n * D_ + bk + tx] = l;
    }
}

// ---------------------------------------------------------------------------
// GEMM common: BM=128, BN=64, BK=64, 2-stage cp.async, ONE barrier/tile.
// ---------------------------------------------------------------------------
#define KSTR 72
#define STG_AHI 0
#define STG_ALO 18432
#define STG_WHI 36864
#define STG_WLO 46080
#define STG_SZ  55296
#define NTILE   16
#define GS_TOT  (2 * STG_SZ)   // 110592

#define GEMM_LOAD_TILE(kt, s)                                                  \
    do {                                                                       \
        const u32 sb_ = sbase + (u32)((s) * STG_SZ);                           \
        const int kb_ = (kt) * 64;                                             \
        _Pragma("unroll")                                                      \
        for (int it = 0; it < 4; it++) {                                       \
            const int c = tid + it * 256;                                      \
            const int row = c >> 3;                                            \
            const int c8  = (c & 7) * 8;                                       \
            const u32 so = (u32)((row * KSTR + c8) * 2);                       \
            const size_t gi = (size_t)(m0 + row) * D_ + kb_ + c8;              \
            cpasync16(sb_ + STG_AHI + so, Ahi + gi);                           \
            cpasync16(sb_ + STG_ALO + so, Alo + gi);                           \
        }                                                                      \
        _Pragma("unroll")                                                      \
        for (int it = 0; it < 2; it++) {                                       \
            const int c = tid + it * 256;                                      \
            const int row = c >> 3;                                            \
            const int c8  = (c & 7) * 8;                                       \
            const u32 so = (u32)((row * KSTR + c8) * 2);                       \
            const size_t gi = (size_t)(n0 + row) * D_ + kb_ + c8;              \
            cpasync16(sb_ + STG_WHI + so, WhiT + gi);                          \
            cpasync16(sb_ + STG_WLO + so, WloT + gi);                          \
        }                                                                      \
    } while (0)

#define GEMM_MAINLOOP()                                                        \
    GEMM_LOAD_TILE(0, 0);                                                      \
    CP_COMMIT();                                                               \
    for (int kt = 0; kt < NTILE; kt++) {                                       \
        CP_WAIT(0);                                                            \
        __syncthreads();                                                       \
        if (kt + 1 < NTILE) { GEMM_LOAD_TILE(kt + 1, (kt + 1) & 1); CP_COMMIT(); } \
        const u32 sb = sbase + (u32)((kt & 1) * STG_SZ);                       \
        const u32 aHi0 = sb + STG_AHI + aOff;                                  \
        const u32 aLo0 = sb + STG_ALO + aOff;                                  \
        const u32 bHi0 = sb + STG_WHI + bOff;                                  \
        const u32 bLo0 = sb + STG_WLO + bOff;                                  \
        _Pragma("unroll")                                                      \
        for (int ks = 0; ks < 4; ks++) {                                       \
            const u32 ko = ks * 32;                                            \
            u32 ah[2][4], al[2][4], bh[8], bl[8];                              \
            ldsm4(ah[0][0], ah[0][1], ah[0][2], ah[0][3], aHi0 + ko);          \
            ldsm4(ah[1][0], ah[1][1], ah[1][2], ah[1][3], aHi0 + step16 + ko); \
            ldsm4(al[0][0], al[0][1], al[0][2], al[0][3], aLo0 + ko);          \
            ldsm4(al[1][0], al[1][1], al[1][2], al[1][3], aLo0 + step16 + ko); \
            ldsm4(bh[0], bh[1], bh[2], bh[3], bHi0 + ko);                      \
            ldsm4(bh[4], bh[5], bh[6], bh[7], bHi0 + step16 + ko);             \
            ldsm4(bl[0], bl[1], bl[2], bl[3], bLo0 + ko);                      \
            ldsm4(bl[4], bl[5], bl[6], bl[7], bLo0 + step16 + ko);             \
            _Pragma("unroll")                                                  \
            for (int mt = 0; mt < 2; mt++)                                     \
                _Pragma("unroll")                                              \
                for (int nt = 0; nt < 4; nt++) {                               \
                    mma16816(acc[mt][nt], ah[mt], &bh[nt * 2]);                \
                    mma16816(acc[mt][nt], ah[mt], &bl[nt * 2]);                \
                    mma16816(acc[mt][nt], al[mt], &bh[nt * 2]);                \
                }                                                              \
        }                                                                      \
        if (kt + 1 < NTILE) __syncthreads();                                   \
    }

// NOTE on the trailing guard barrier: with 2 stages, the NEXT iteration's
// prefetch (issued after that iteration's leading sync) targets the stage this
// iteration just read — so reads must complete before any warp issues it. The
// leading sync of iteration kt+1 provides exactly that ordering; the extra
// trailing sync above is required ONLY because the prefetch for kt+1 was
// issued in THIS iteration before compute. We issue prefetch kt+1 (stage
// (kt+1)&1 != kt&1) before compute(kt): distinct stages, no conflict; the
// trailing sync instead orders compute(kt) reads before iteration kt+1's
// prefetch of stage (kt+2)&1 == kt&1. Net: still one sync saved vs R13? No —
// keep both semantics correct: leading sync + trailing sync only when looping.
// (Trailing sync kept conditionally; prefetch overlap is preserved.)

// ---- merged QKV projection: gridDim.z selects weight/output/mode -----------
__global__ __launch_bounds__(256) void qkv_gemm(
    const bf16* __restrict__ Ahi, const bf16* __restrict__ Alo,
    const bf16* __restrict__ wT,
    bf16* __restrict__ qhi, bf16* __restrict__ qlo,
    bf16* __restrict__ khi, bf16* __restrict__ klo,
    bf16* __restrict__ vthi, bf16* __restrict__ vtlo) {
    extern __shared__ __align__(16) char gsm[];
    const u32 sbase = smem_u32(gsm);
    const int tid  = threadIdx.x;
    const int wid  = tid >> 5;
    const int lane = tid & 31;
    const int m0 = blockIdx.y * 128;
    const int n0 = blockIdx.x * 64;
    const int z  = blockIdx.z;
    const int wm = (wid >> 1) * 32;
    const int wn = (wid & 1) * 32;

    const bf16* WhiT = wT + (size_t)(2 * z)     * D_ * D_;
    const bf16* WloT = wT + (size_t)(2 * z + 1) * D_ * D_;

    const int aRow = lane & 15;
    const int aK   = (lane >> 4) * 8;
    const int bN   = ((lane >> 4) << 3) | (lane & 7);
    const int bK   = ((lane >> 3) & 1) * 8;
    const u32 aOff = (u32)(((wm + aRow) * KSTR + aK) * 2);
    const u32 bOff = (u32)(((wn + bN) * KSTR + bK) * 2);
    const u32 step16 = 16 * KSTR * 2;

    float acc[2][4][4];
#pragma unroll
    for (int mt = 0; mt < 2; mt++)
#pragma unroll
        for (int nt = 0; nt < 4; nt++)
#pragma unroll
            for (int r = 0; r < 4; r++) acc[mt][nt][r] = 0.f;

    GEMM_MAINLOOP();

    const float oscale = (z == 0) ? 0.125f : 1.0f;
    const int r  = lane >> 2;
    const int cc = (lane & 3) * 2;
#pragma unroll
    for (int mt = 0; mt < 2; mt++) {
        const int mrow = m0 + wm + mt * 16 + r;
        const int b = mrow >> 11;
        const int t = mrow & 2047;
        const int h = n0 >> 6;
#pragma unroll
        for (int nt = 0; nt < 4; nt++) {
            const int ncol = wn + nt * 8 + cc;
            const float a0 = acc[mt][nt][0] * oscale, a1 = acc[mt][nt][1] * oscale;
            const float a2 = acc[mt][nt][2] * oscale, a3 = acc[mt][nt][3] * oscale;
            if (z < 2) {   // Q or K: (B,H,T,DH) hi/lo
                bf16* hi = (z == 0) ? qhi : khi;
                bf16* lo = (z == 0) ? qlo : klo;
                const size_t base = ((size_t)((b * H_ + h) * T_ + t)) * DH_ + ncol;
                u32 h01, l01, h23, l23;
                split2(a0, a1, h01, l01);
                split2(a2, a3, h23, l23);
                *(u32*)&hi[base] = h01;
                *(u32*)&lo[base] = l01;
                *(u32*)&hi[base + 8 * DH_] = h23;
                *(u32*)&lo[base + 8 * DH_] = l23;
            } else {       // V: transposed (B,H,DH,T) hi/lo
                const size_t r0b = ((size_t)((b * H_ + h) * DH_ + ncol)) * T_;
                const size_t r1b = r0b + T_;
                const float f[4] = {a0, a1, a2, a3};
                const size_t ix[4] = {r0b + t, r1b + t, r0b + t + 8, r1b + t + 8};
#pragma unroll
                for (int e = 0; e < 4; e++) {
                    const bf16 hv = __float2bfloat16(f[e]);
                    vthi[ix[e]] = hv;
                    vtlo[ix[e]] = __float2bfloat16(f[e] - __bfloat162float(hv));
                }
            }
        }
    }
}

// ---- output projection: f32 row-major ---------------------------------------
__global__ __launch_bounds__(256) void o_gemm(
    const bf16* __restrict__ Ahi, const bf16* __restrict__ Alo,
    const bf16* __restrict__ WhiT, const bf16* __restrict__ WloT,
    float* __restrict__ Y) {
    extern __shared__ __align__(16) char gsm[];
    const u32 sbase = smem_u32(gsm);
    const int tid  = threadIdx.x;
    const int wid  = tid >> 5;
    const int lane = tid & 31;
    const int m0 = blockIdx.y * 128;
    const int n0 = blockIdx.x * 64;
    const int wm = (wid >> 1) * 32;
    const int wn = (wid & 1) * 32;

    const int aRow = lane & 15;
    const int aK   = (lane >> 4) * 8;
    const int bN   = ((lane >> 4) << 3) | (lane & 7);
    const int bK   = ((lane >> 3) & 1) * 8;
    const u32 aOff = (u32)(((wm + aRow) * KSTR + aK) * 2);
    const u32 bOff = (u32)(((wn + bN) * KSTR + bK) * 2);
    const u32 step16 = 16 * KSTR * 2;

    float acc[2][4][4];
#pragma unroll
    for (int mt = 0; mt < 2; mt++)
#pragma unroll
        for (int nt = 0; nt < 4; nt++)
#pragma unroll
            for (int r = 0; r < 4; r++) acc[mt][nt][r] = 0.f;

    GEMM_MAINLOOP();

    const int r  = lane >> 2;
    const int cc = (lane & 3) * 2;
#pragma unroll
    for (int mt = 0; mt < 2; mt++) {
        const int mrow = m0 + wm + mt * 16 + r;
#pragma unroll
        for (int nt = 0; nt < 4; nt++) {
            const int ncol = wn + nt * 8 + cc;
            *(float2*)&Y[(size_t)mrow * 1024 + n0 + ncol] =
                make_float2(acc[mt][nt][0], acc[mt][nt][1]);
            *(float2*)&Y[(size_t)(mrow + 8) * 1024 + n0 + ncol] =
                make_float2(acc[mt][nt][2], acc[mt][nt][3]);
        }
    }
}

// ---------------------------------------------------------------------------
// Pipelined HMMA flash attention — single-barrier variant.
// ---------------------------------------------------------------------------
#define QSTR 72
#define VSTR 136
#define AQHI 0
#define AQLO 18432
#define ASTG 36864
#define SK_HI 0
#define SK_LO 18432
#define SV_HI 36864
#define SV_LO 54272
#define ASTG_SZ 71680
#define ATT_SMEM (ASTG + 2 * ASTG_SZ)   // 180224

__global__ __launch_bounds__(256, 1) void attn_hmma(
    const bf16* __restrict__ Qhi, const bf16* __restrict__ Qlo,
    const bf16* __restrict__ Khi, const bf16* __restrict__ Klo,
    const bf16* __restrict__ VThi, const bf16* __restrict__ VTlo,
    bf16* __restrict__ Ohi, bf16* __restrict__ Olo) {
    extern __shared__ __align__(16) char smc[];
    const u32 sb = smem_u32(smc);

    const int qb = gridDim.x - 1 - blockIdx.x;
    const int bh = blockIdx.y;
    const int tid  = threadIdx.x;
    const int wid  = tid >> 5;
    const int lane = tid & 31;
    const int wq = wid * 16;

    const bf16* Kg0 = Khi + (size_t)bh * T_ * DH_;
    const bf16* Kg1 = Klo + (size_t)bh * T_ * DH_;
    const bf16* Vg0 = VThi + (size_t)bh * DH_ * T_;
    const bf16* Vg1 = VTlo + (size_t)bh * DH_ * T_;

    auto stage_kv = [&](int kb, int s) {
        const u32 st = sb + ASTG + (u32)(s * ASTG_SZ);
#pragma unroll
        for (int it = 0; it < 4; it++) {
            const int c = tid + it * 256;
            {
                const int row = c >> 3, c16 = (c & 7) * 8;
                const size_t gi = (size_t)(kb * 128 + row) * DH_ + c16;
                const u32 so = (u32)((row * QSTR + c16) * 2);
                cpasync16(st + SK_HI + so, Kg0 + gi);
                cpasync16(st + SK_LO + so, Kg1 + gi);
            }
            {
                const int row = c >> 4, c16 = (c & 15) * 8;
                const size_t gi = (size_t)row * T_ + kb * 128 + c16;
                const u32 so = (u32)((row * VSTR + c16) * 2);
                cpasync16(st + SV_HI + so, Vg0 + gi);
                cpasync16(st + SV_LO + so, Vg1 + gi);
            }
        }
    };

    const bf16* Qg0 = Qhi + ((size_t)bh * T_ + qb * 128) * DH_;
    const bf16* Qg1 = Qlo + ((size_t)bh * T_ + qb * 128) * DH_;
#pragma unroll
    for (int it = 0; it < 4; it++) {
        const int c = tid + it * 256;
        const int row = c >> 3;
        const int k8  = (c & 7) * 8;
        *(uint4*)(smc + AQHI + (row * QSTR + k8) * 2) = *(const uint4*)&Qg0[row * 64 + k8];
        *(uint4*)(smc + AQLO + (row * QSTR + k8) * 2) = *(const uint4*)&Qg1[row * 64 + k8];
    }
    stage_kv(0, 0); CP_COMMIT();
    __syncthreads();

    const int aRow = lane & 15;
    const int aK   = (lane >> 4) * 8;
    const u32 qa = sb + AQHI + ((wq + aRow) * QSTR + aK) * 2;
    u32 qf[2][4][4];
#pragma unroll
    for (int ks = 0; ks < 4; ks++) {
        ldsm4(qf[0][ks][0], qf[0][ks][1], qf[0][ks][2], qf[0][ks][3], qa + ks * 32);
        ldsm4(qf[1][ks][0], qf[1][ks][1], qf[1][ks][2], qf[1][ks][3],
              qa + (AQLO - AQHI) + ks * 32);
    }

    float oacc[8][4];
#pragma unroll
    for (int nt = 0; nt < 8; nt++)
#pragma unroll
        for (int r = 0; r < 4; r++) oacc[nt][r] = 0.f;
    float mrw[2] = {-1e30f, -1e30f}, lrw[2] = {0.f, 0.f};

    const int bN = ((lane >> 4) << 3) | (lane & 7);
    const int bK = ((lane >> 3) & 1) * 8;
    const u32 kOff = (u32)((bN * QSTR + bK) * 2);
    const u32 vOff = (u32)((bN * VSTR + bK) * 2);
    const int r0 = lane >> 2;
    const int cb = (lane & 3) * 2;

    for (int kb = 0; kb <= qb; kb++) {
        CP_WAIT(0);          // tile kb resident
        __syncthreads();     // + all warps done reading the other stage
        if (kb + 1 <= qb) { stage_kv(kb + 1, (kb + 1) & 1); CP_COMMIT(); }

        const u32 st = sb + ASTG + (u32)((kb & 1) * ASTG_SZ);
        const u32 kba = st + SK_HI + kOff;
        const u32 vba = st + SV_HI + vOff;

        float sacc[16][4];
#pragma unroll
        for (int nt = 0; nt < 16; nt++)
#pragma unroll
            for (int r = 0; r < 4; r++) sacc[nt][r] = 0.f;

#pragma unroll
        for (int nc = 0; nc < 8; nc++) {
            const u32 nco = (u32)(nc * 16 * QSTR * 2);
#pragma unroll
            for (int ks = 0; ks < 4; ks++) {
                u32 kh[4], kl[4];
                ldsm4(kh[0], kh[1], kh[2], kh[3], kba + nco + ks * 32);
                ldsm4(kl[0], kl[1], kl[2], kl[3],
                      kba + (SK_LO - SK_HI) + nco + ks * 32);
                mma16816(sacc[2 * nc],     qf[0][ks], &kh[0]);
                mma16816(sacc[2 * nc],     qf[0][ks], &kl[0]);
                mma16816(sacc[2 * nc],     qf[1][ks], &kh[0]);
                mma16816(sacc[2 * nc + 1], qf[0][ks], &kh[2]);
                mma16816(sacc[2 * nc + 1], qf[0][ks], &kl[2]);
                mma16816(sacc[2 * nc + 1], qf[1][ks], &kh[2]);
            }
        }

        const bool diag = (kb == qb);
        float alpha[2];
#pragma unroll
        for (int rh = 0; rh < 2; rh++) {
            const int rl = wq + r0 + rh * 8;
            float mx = -1e30f;
#pragma unroll
            for (int nt = 0; nt < 16; nt++) {
                float v0 = sacc[nt][2 * rh];
                float v1 = sacc[nt][2 * rh + 1];
                if (diag) {
                    const int col = nt * 8 + cb;
                    if (col > rl)     v0 = -1e30f;
                    if (col + 1 > rl) v1 = -1e30f;
                }
                sacc[nt][2 * rh]     = v0;
                sacc[nt][2 * rh + 1] = v1;
                mx = fmaxf(mx, fmaxf(v0, v1));
            }
            mx = fmaxf(mx, __shfl_xor_sync(0xffffffffu, mx, 1));
            mx = fmaxf(mx, __shfl_xor_sync(0xffffffffu, mx, 2));
            const float mnew = fmaxf(mrw[rh], mx);
            alpha[rh] = __expf(mrw[rh] - mnew);
            float rs = 0.f;
#pragma unroll
            for (int nt = 0; nt < 16; nt++) {
                const float p0 = __expf(sacc[nt][2 * rh]     - mnew);
                const float p1 = __expf(sacc[nt][2 * rh + 1] - mnew);
                sacc[nt][2 * rh]     = p0;
                sacc[nt][2 * rh + 1] = p1;
                rs += p0 + p1;
            }
            rs += __shfl_xor_sync(0xffffffffu, rs, 1);
            rs += __shfl_xor_sync(0xffffffffu, rs, 2);
            lrw[rh] = lrw[rh] * alpha[rh] + rs;
            mrw[rh] = mnew;
        }
#pragma unroll
        for (int nt = 0; nt < 8; nt++) {
            oacc[nt][0] *= alpha[0];
            oacc[nt][1] *= alpha[0];
            oacc[nt][2] *= alpha[1];
            oacc[nt][3] *= alpha[1];
        }

#pragma unroll
        for (int ks = 0; ks < 8; ks++) {
            u32 ph[4], pl[4];
            split2(sacc[2 * ks][0],     sacc[2 * ks][1],     ph[0], pl[0]);
            split2(sacc[2 * ks][2],     sacc[2 * ks][3],     ph[1], pl[1]);
            split2(sacc[2 * ks + 1][0], sacc[2 * ks + 1][1], ph[2], pl[2]);
            split2(sacc[2 * ks + 1][2], sacc[2 * ks + 1][3], ph[3], pl[3]);
#pragma unroll
            for (int nc = 0; nc < 4; nc++) {
                const u32 nco = (u32)(nc * 16 * VSTR * 2);
                u32 vh[4], vl[4];
                ldsm4(vh[0], vh[1], vh[2], vh[3], vba + nco + ks * 32);
                ldsm4(vl[0], vl[1], vl[2], vl[3],
                      vba + (SV_LO - SV_HI) + nco + ks * 32);
                mma16816(oacc[2 * nc],     ph, &vh[0]);
                mma16816(oacc[2 * nc],     ph, &vl[0]);
                mma16816(oacc[2 * nc],     pl, &vh[0]);
                mma16816(oacc[2 * nc + 1], ph, &vh[2]);
                mma16816(oacc[2 * nc + 1], ph, &vl[2]);
                mma16816(oacc[2 * nc + 1], pl, &vh[2]);
            }
        }
    }

    const float inv0 = 1.f / lrw[0];
    const float inv1 = 1.f / lrw[1];
    const int b  = bh >> 4;
    const int hh = bh & 15;
    const int t0 = qb * 128 + wq + r0;
#pragma unroll
    for (int nt = 0; nt < 8; nt++) {
        const int col = hh * 64 + nt * 8 + cb;
        u32 h01, l01, h23, l23;
        split2(oacc[nt][0] * inv0, oacc[nt][1] * inv0, h01, l01);
        split2(oacc[nt][2] * inv1, oacc[nt][3] * inv1, h23, l23);
        const size_t i0 = ((size_t)(b * T_ + t0)) * D_ + col;
        const size_t i1 = ((size_t)(b * T_ + t0 + 8)) * D_ + col;
        *(u32*)&Ohi[i0] = h01;
        *(u32*)&Olo[i0] = l01;
        *(u32*)&Ohi[i1] = h23;
        *(u32*)&Olo[i1] = l23;
    }
}

// ---------------------------------------------------------------------------
// Host launcher (graph-capturable)
// ---------------------------------------------------------------------------
extern "C" void kernel_launch(void* const* d_in, const int* in_sizes, int n_in,
                              void* d_out, int out_size) {
    (void)in_sizes; (void)n_in; (void)out_size;
    const float* x = (const float*)d_in[0];
    const float* W[4] = {(const float*)d_in[1], (const float*)d_in[2],
                         (const float*)d_in[3], (const float*)d_in[4]};
    float* out = (float*)d_out;

    bf16 *xhi, *xlo, *wT, *qhi, *qlo, *khi, *klo, *vthi, *vtlo, *ahi, *alo;
    cudaGetSymbolAddress((void**)&xhi,  g_xhi);
    cudaGetSymbolAddress((void**)&xlo,  g_xlo);
    cudaGetSymbolAddress((void**)&wT,   g_wT);
    cudaGetSymbolAddress((void**)&qhi,  g_qhi);
    cudaGetSymbolAddress((void**)&qlo,  g_qlo);
    cudaGetSymbolAddress((void**)&khi,  g_khi);
    cudaGetSymbolAddress((void**)&klo,  g_klo);
    cudaGetSymbolAddress((void**)&vthi, g_vthi);
    cudaGetSymbolAddress((void**)&vtlo, g_vtlo);
    cudaGetSymbolAddress((void**)&ahi,  g_ahi);
    cudaGetSymbolAddress((void**)&alo,  g_alo);

    cudaFuncSetAttribute(qkv_gemm, cudaFuncAttributeMaxDynamicSharedMemorySize, GS_TOT);
    cudaFuncSetAttribute(o_gemm,   cudaFuncAttributeMaxDynamicSharedMemorySize, GS_TOT);
    cudaFuncSetAttribute(attn_hmma, cudaFuncAttributeMaxDynamicSharedMemorySize, ATT_SMEM);

    // --- pre-pass ---
    split_kernel<<<M_ * D_ / 1024, 256>>>(x, xhi, xlo);
    const dim3 tgrid(D_ / 32, D_ / 32);
    for (int w = 0; w < 4; w++)
        tsplit_kernel<<<tgrid, 256>>>(W[w],
                                      wT + (size_t)(2 * w)     * D_ * D_,
                                      wT + (size_t)(2 * w + 1) * D_ * D_);

    // --- Q,K,V projections in ONE launch (z selects weight/output) ---
    const dim3 qkvgrid(D_ / 64, M_ / 128, 3);   // (16, 32, 3) = 1536 CTAs
    qkv_gemm<<<qkvgrid, 256, GS_TOT>>>(xhi, xlo, wT,
                                       qhi, qlo, khi, klo, vthi, vtlo);

    // --- attention ---
    const dim3 agrid(T_ / 128, BH_);
    attn_hmma<<<agrid, 256, ATT_SMEM>>>(qhi, qlo, khi, klo, vthi, vtlo, ahi, alo);

    // --- output projection ---
    const dim3 ogrid(D_ / 64, M_ / 128);
    o_gemm<<<ogrid, 256, GS_TOT>>>(ahi, alo,
        wT + 6 * (size_t)D_ * D_, wT + 7 * (size_t)D_ * D_, out);
}

// round 17
// speedup vs baseline: 1.2652x; 1.0884x over previous
#include <cuda_runtime.h>
#include <cuda_bf16.h>
#include <cuda_fp16.h>
#include <cstdint>
#include <math.h>

#define B_  2
#define T_  2048
#define D_  1024
#define H_  16
#define DH_ 64
#define M_  (B_ * T_)
#define BH_ (B_ * H_)

typedef unsigned long long u64;
typedef unsigned int u32;
typedef __nv_bfloat16 bf16;
typedef __half f16;

// ---------------------------------------------------------------------------
// Generic tensor-core + cp.async PTX (sm_80+, legal under compute_103)
// ---------------------------------------------------------------------------
__device__ __forceinline__ u32 smem_u32(const void* p) {
    u32 a;
    asm("{ .reg .u64 t; cvta.to.shared.u64 t, %1; cvt.u32.u64 %0, t; }"
        : "=r"(a) : "l"(p));
    return a;
}
__device__ __forceinline__ void ldsm4(u32& r0, u32& r1, u32& r2, u32& r3, u32 addr) {
    asm volatile("ldmatrix.sync.aligned.m8n8.x4.shared.b16 {%0,%1,%2,%3}, [%4];"
                 : "=r"(r0), "=r"(r1), "=r"(r2), "=r"(r3) : "r"(addr));
}
__device__ __forceinline__ void mma16816(float* c, const u32* a, const u32* b) {
    asm volatile("mma.sync.aligned.m16n8k16.row.col.f32.bf16.bf16.f32 "
                 "{%0,%1,%2,%3}, {%4,%5,%6,%7}, {%8,%9}, {%0,%1,%2,%3};"
                 : "+f"(c[0]), "+f"(c[1]), "+f"(c[2]), "+f"(c[3])
                 : "r"(a[0]), "r"(a[1]), "r"(a[2]), "r"(a[3]),
                   "r"(b[0]), "r"(b[1]));
}
__device__ __forceinline__ void mma16816h(float* c, const u32* a, const u32* b) {
    asm volatile("mma.sync.aligned.m16n8k16.row.col.f32.f16.f16.f32 "
                 "{%0,%1,%2,%3}, {%4,%5,%6,%7}, {%8,%9}, {%0,%1,%2,%3};"
                 : "+f"(c[0]), "+f"(c[1]), "+f"(c[2]), "+f"(c[3])
                 : "r"(a[0]), "r"(a[1]), "r"(a[2]), "r"(a[3]),
                   "r"(b[0]), "r"(b[1]));
}
__device__ __forceinline__ void cpasync16(u32 s, const void* g) {
    asm volatile("cp.async.cg.shared.global [%0], [%1], 16;" :: "r"(s), "l"(g));
}
#define CP_COMMIT()  asm volatile("cp.async.commit_group;" ::: "memory")
#define CP_WAIT(n)   asm volatile("cp.async.wait_group " #n ";" ::: "memory")

__device__ __forceinline__ void split2(float a, float b, u32& hi, u32& lo) {
    __nv_bfloat162 h = __float22bfloat162_rn(make_float2(a, b));
    float2 hf = __bfloat1622float2(h);
    __nv_bfloat162 l = __float22bfloat162_rn(make_float2(a - hf.x, b - hf.y));
    hi = *(u32*)&h;
    lo = *(u32*)&l;
}
__device__ __forceinline__ void split2h(float a, float b, u32& hi, u32& lo) {
    __half2 h = __float22half2_rn(make_float2(a, b));
    float2 hf = __half22float2(h);
    __half2 l = __float22half2_rn(make_float2(a - hf.x, b - hf.y));
    hi = *(u32*)&h;
    lo = *(u32*)&l;
}

// ---------------------------------------------------------------------------
// Scratch
// ---------------------------------------------------------------------------
__device__ __align__(16) bf16 g_xhi[M_ * D_];
__device__ __align__(16) bf16 g_xlo[M_ * D_];
__device__ __align__(16) f16  g_xh16[M_ * D_];
__device__ __align__(16) f16  g_xl16[M_ * D_];
__device__ __align__(16) bf16 g_wT[4 * D_ * D_];            // Wq hi/lo, Wk hi/lo [N][K]
__device__ __align__(16) f16  g_w16[2 * D_ * D_];           // Wv hi, Wo hi [N][K]
__device__ __align__(16) bf16 g_qhi[BH_ * T_ * DH_];        // pre-scaled by 0.125
__device__ __align__(16) bf16 g_qlo[BH_ * T_ * DH_];
__device__ __align__(16) bf16 g_khi[BH_ * T_ * DH_];
__device__ __align__(16) bf16 g_klo[BH_ * T_ * DH_];
__device__ __align__(16) bf16 g_vthi[BH_ * DH_ * T_];       // V^T (B,H,DH,T)
__device__ __align__(16) bf16 g_vtlo[BH_ * DH_ * T_];
__device__ __align__(16) f16  g_ah16[M_ * D_];              // attn out fp16 hi/lo
__device__ __align__(16) f16  g_al16[M_ * D_];

// ---------------------------------------------------------------------------
// Pre-pass: x -> bf16 hi/lo (for Q,K proj) + fp16 hi/lo (for V proj)
// ---------------------------------------------------------------------------
__global__ __launch_bounds__(256) void split_kernel(const float* __restrict__ src,
                                                    bf16* __restrict__ bhi,
                                                    bf16* __restrict__ blo,
                                                    f16* __restrict__ hhi,
                                                    f16* __restrict__ hlo) {
    const int i = (blockIdx.x * 256 + threadIdx.x) * 4;
    const float4 v = *(const float4*)&src[i];
    const float f[4] = {v.x, v.y, v.z, v.w};
    bf16 bh[4], bl[4];
    f16  hh[4], hl[4];
#pragma unroll
    for (int j = 0; j < 4; j++) {
        bh[j] = __float2bfloat16(f[j]);
        bl[j] = __float2bfloat16(f[j] - __bfloat162float(bh[j]));
        hh[j] = __float2half_rn(f[j]);
        hl[j] = __float2half_rn(f[j] - __half2float(hh[j]));
    }
    *(uint2*)&bhi[i] = *(const uint2*)bh;
    *(uint2*)&blo[i] = *(const uint2*)bl;
    *(uint2*)&hhi[i] = *(const uint2*)hh;
    *(uint2*)&hlo[i] = *(const uint2*)hl;
}

// ---------------------------------------------------------------------------
// Pre-pass: W[K][N] fp32 -> [N][K] splits. z=0,1: bf16 hi/lo (Wq,Wk).
// z=2,3: fp16 hi only (Wv,Wo).
// ---------------------------------------------------------------------------
__global__ __launch_bounds__(256) void tsplit_kernel(
    const float* __restrict__ W0, const float* __restrict__ W1,
    const float* __restrict__ W2, const float* __restrict__ W3,
    bf16* __restrict__ wT, f16* __restrict__ w16) {
    __shared__ float t[32][33];
    const int z = blockIdx.z;
    const float* W = (z == 0) ? W0 : (z == 1) ? W1 : (z == 2) ? W2 : W3;
    const int tx = threadIdx.x & 31;
    const int ty = threadIdx.x >> 5;
    const int bn = blockIdx.x * 32;
    const int bk = blockIdx.y * 32;
#pragma unroll
    for (int i = 0; i < 4; i++)
        t[ty + 8 * i][tx] = W[(size_t)(bk + ty + 8 * i) * D_ + bn + tx];
    __syncthreads();
#pragma unroll
    for (int i = 0; i < 4; i++) {
        const int n = bn + ty + 8 * i;
        const float v = t[tx][ty + 8 * i];
        if (z < 2) {
            bf16* hiT = wT + (size_t)(2 * z) * D_ * D_;
            bf16* loT = wT + (size_t)(2 * z + 1) * D_ * D_;
            const bf16 h = __float2bfloat16(v);
            hiT[(size_t)n * D_ + bk + tx] = h;
            loT[(size_t)n * D_ + bk + tx] = __float2bfloat16(v - __bfloat162float(h));
        } else {
            f16* hiT = w16 + (size_t)(z - 2) * D_ * D_;
            hiT[(size_t)n * D_ + bk + tx] = __float2half_rn(v);
        }
    }
}

// ---------------------------------------------------------------------------
// GEMM common: BM=128, BN=64, BK=64, 2-stage cp.async.
// ---------------------------------------------------------------------------
#define KSTR 72
#define STG_AHI 0
#define STG_ALO 18432
#define STG_WHI 36864
#define STG_WLO 46080
#define STG_SZ  55296
#define NTILE   16
#define GS_TOT  (2 * STG_SZ)   // 110592

// bf16 3-product loader/mainloop (validated)
#define GEMM_LOAD_TILE(kt, s)                                                  \
    do {                                                                       \
        const u32 sb_ = sbase + (u32)((s) * STG_SZ);                           \
        const int kb_ = (kt) * 64;                                             \
        _Pragma("unroll")                                                      \
        for (int it = 0; it < 4; it++) {                                       \
            const int c = tid + it * 256;                                      \
            const int row = c >> 3;                                            \
            const int c8  = (c & 7) * 8;                                       \
            const u32 so = (u32)((row * KSTR + c8) * 2);                       \
            const size_t gi = (size_t)(m0 + row) * D_ + kb_ + c8;              \
            cpasync16(sb_ + STG_AHI + so, Ahi + gi);                           \
            cpasync16(sb_ + STG_ALO + so, Alo + gi);                           \
        }                                                                      \
        _Pragma("unroll")                                                      \
        for (int it = 0; it < 2; it++) {                                       \
            const int c = tid + it * 256;                                      \
            const int row = c >> 3;                                            \
            const int c8  = (c & 7) * 8;                                       \
            const u32 so = (u32)((row * KSTR + c8) * 2);                       \
            const size_t gi = (size_t)(n0 + row) * D_ + kb_ + c8;              \
            cpasync16(sb_ + STG_WHI + so, WhiT + gi);                          \
            cpasync16(sb_ + STG_WLO + so, WloT + gi);                          \
        }                                                                      \
    } while (0)

#define GEMM_MAINLOOP()                                                        \
    GEMM_LOAD_TILE(0, 0);                                                      \
    CP_COMMIT();                                                               \
    for (int kt = 0; kt < NTILE; kt++) {                                       \
        CP_WAIT(0);                                                            \
        __syncthreads();                                                       \
        if (kt + 1 < NTILE) { GEMM_LOAD_TILE(kt + 1, (kt + 1) & 1); CP_COMMIT(); } \
        const u32 sb = sbase + (u32)((kt & 1) * STG_SZ);                       \
        const u32 aHi0 = sb + STG_AHI + aOff;                                  \
        const u32 aLo0 = sb + STG_ALO + aOff;                                  \
        const u32 bHi0 = sb + STG_WHI + bOff;                                  \
        const u32 bLo0 = sb + STG_WLO + bOff;                                  \
        _Pragma("unroll")                                                      \
        for (int ks = 0; ks < 4; ks++) {                                       \
            const u32 ko = ks * 32;                                            \
            u32 ah[2][4], al[2][4], bh[8], bl[8];                              \
            ldsm4(ah[0][0], ah[0][1], ah[0][2], ah[0][3], aHi0 + ko);          \
            ldsm4(ah[1][0], ah[1][1], ah[1][2], ah[1][3], aHi0 + step16 + ko); \
            ldsm4(al[0][0], al[0][1], al[0][2], al[0][3], aLo0 + ko);          \
            ldsm4(al[1][0], al[1][1], al[1][2], al[1][3], aLo0 + step16 + ko); \
            ldsm4(bh[0], bh[1], bh[2], bh[3], bHi0 + ko);                      \
            ldsm4(bh[4], bh[5], bh[6], bh[7], bHi0 + step16 + ko);             \
            ldsm4(bl[0], bl[1], bl[2], bl[3], bLo0 + ko);                      \
            ldsm4(bl[4], bl[5], bl[6], bl[7], bLo0 + step16 + ko);             \
            _Pragma("unroll")                                                  \
            for (int mt = 0; mt < 2; mt++)                                     \
                _Pragma("unroll")                                              \
                for (int nt = 0; nt < 4; nt++) {                               \
                    mma16816(acc[mt][nt], ah[mt], &bh[nt * 2]);                \
                    mma16816(acc[mt][nt], ah[mt], &bl[nt * 2]);                \
                    mma16816(acc[mt][nt], al[mt], &bh[nt * 2]);                \
                }                                                              \
        }                                                                      \
        if (kt + 1 < NTILE) __syncthreads();                                   \
    }

// fp16 2-product loader/mainloop: A full (hi+lo) x B hi only.
#define GEMM_LOAD_TILE_F16(kt, s)                                              \
    do {                                                                       \
        const u32 sb_ = sbase + (u32)((s) * STG_SZ);                           \
        const int kb_ = (kt) * 64;                                             \
        _Pragma("unroll")                                                      \
        for (int it = 0; it < 4; it++) {                                       \
            const int c = tid + it * 256;                                      \
            const int row = c >> 3;                                            \
            const int c8  = (c & 7) * 8;                                       \
            const u32 so = (u32)((row * KSTR + c8) * 2);                       \
            const size_t gi = (size_t)(m0 + row) * D_ + kb_ + c8;              \
            cpasync16(sb_ + STG_AHI + so, Ah16 + gi);                          \
            cpasync16(sb_ + STG_ALO + so, Al16 + gi);                          \
        }                                                                      \
        _Pragma("unroll")                                                      \
        for (int it = 0; it < 2; it++) {                                       \
            const int c = tid + it * 256;                                      \
            const int row = c >> 3;                                            \
            const int c8  = (c & 7) * 8;                                       \
            const u32 so = (u32)((row * KSTR + c8) * 2);                       \
            const size_t gi = (size_t)(n0 + row) * D_ + kb_ + c8;              \
            cpasync16(sb_ + STG_WHI + so, Wh16 + gi);                          \
        }                                                                      \
    } while (0)

#define GEMM_MAINLOOP_F16()                                                    \
    GEMM_LOAD_TILE_F16(0, 0);                                                  \
    CP_COMMIT();                                                               \
    for (int kt = 0; kt < NTILE; kt++) {                                       \
        CP_WAIT(0);                                                            \
        __syncthreads();                                                       \
        if (kt + 1 < NTILE) { GEMM_LOAD_TILE_F16(kt + 1, (kt + 1) & 1); CP_COMMIT(); } \
        const u32 sb = sbase + (u32)((kt & 1) * STG_SZ);                       \
        const u32 aHi0 = sb + STG_AHI + aOff;                                  \
        const u32 aLo0 = sb + STG_ALO + aOff;                                  \
        const u32 bHi0 = sb + STG_WHI + bOff;                                  \
        _Pragma("unroll")                                                      \
        for (int ks = 0; ks < 4; ks++) {                                       \
            const u32 ko = ks * 32;                                            \
            u32 ah[2][4], al[2][4], bh[8];                                     \
            ldsm4(ah[0][0], ah[0][1], ah[0][2], ah[0][3], aHi0 + ko);          \
            ldsm4(ah[1][0], ah[1][1], ah[1][2], ah[1][3], aHi0 + step16 + ko); \
            ldsm4(al[0][0], al[0][1], al[0][2], al[0][3], aLo0 + ko);          \
            ldsm4(al[1][0], al[1][1], al[1][2], al[1][3], aLo0 + step16 + ko); \
            ldsm4(bh[0], bh[1], bh[2], bh[3], bHi0 + ko);                      \
            ldsm4(bh[4], bh[5], bh[6], bh[7], bHi0 + step16 + ko);             \
            _Pragma("unroll")                                                  \
            for (int mt = 0; mt < 2; mt++)                                     \
                _Pragma("unroll")                                              \
                for (int nt = 0; nt < 4; nt++) {                               \
                    mma16816h(acc[mt][nt], ah[mt], &bh[nt * 2]);               \
                    mma16816h(acc[mt][nt], al[mt], &bh[nt * 2]);               \
                }                                                              \
        }                                                                      \
        if (kt + 1 < NTILE) __syncthreads();                                   \
    }

#define GEMM_PROLOG()                                                          \
    extern __shared__ __align__(16) char gsm[];                                \
    const u32 sbase = smem_u32(gsm);                                           \
    const int tid  = threadIdx.x;                                              \
    const int wid  = tid >> 5;                                                 \
    const int lane = tid & 31;                                                 \
    const int m0 = blockIdx.y * 128;                                           \
    const int n0 = blockIdx.x * 64;                                            \
    const int wm = (wid >> 1) * 32;                                            \
    const int wn = (wid & 1) * 32;                                             \
    const int aRow = lane & 15;                                                \
    const int aK   = (lane >> 4) * 8;                                          \
    const int bN   = ((lane >> 4) << 3) | (lane & 7);                          \
    const int bK   = ((lane >> 3) & 1) * 8;                                    \
    const u32 aOff = (u32)(((wm + aRow) * KSTR + aK) * 2);                     \
    const u32 bOff = (u32)(((wn + bN) * KSTR + bK) * 2);                       \
    const u32 step16 = 16 * KSTR * 2;                                          \
    float acc[2][4][4];                                                        \
    _Pragma("unroll")                                                          \
    for (int mt = 0; mt < 2; mt++)                                             \
        _Pragma("unroll")                                                      \
        for (int nt = 0; nt < 4; nt++)                                         \
            _Pragma("unroll")                                                  \
            for (int r = 0; r < 4; r++) acc[mt][nt][r] = 0.f;

// ---- merged QKV projection: z=0 Q (bf16), z=1 K (bf16), z=2 V (fp16 2-prod)
__global__ __launch_bounds__(256) void qkv_gemm(
    const bf16* __restrict__ xbhi, const bf16* __restrict__ xblo,
    const f16* __restrict__ Ah16, const f16* __restrict__ Al16,
    const bf16* __restrict__ wT, const f16* __restrict__ Wh16,
    bf16* __restrict__ qhi, bf16* __restrict__ qlo,
    bf16* __restrict__ khi, bf16* __restrict__ klo,
    bf16* __restrict__ vthi, bf16* __restrict__ vtlo) {
    GEMM_PROLOG();
    const int z = blockIdx.z;

    if (z < 2) {
        const bf16* Ahi  = xbhi;
        const bf16* Alo  = xblo;
        const bf16* WhiT = wT + (size_t)(2 * z)     * D_ * D_;
        const bf16* WloT = wT + (size_t)(2 * z + 1) * D_ * D_;
        GEMM_MAINLOOP();
    } else {
        GEMM_MAINLOOP_F16();
    }

    const float oscale = (z == 0) ? 0.125f : 1.0f;
    const int r  = lane >> 2;
    const int cc = (lane & 3) * 2;
#pragma unroll
    for (int mt = 0; mt < 2; mt++) {
        const int mrow = m0 + wm + mt * 16 + r;
        const int b = mrow >> 11;
        const int t = mrow & 2047;
        const int h = n0 >> 6;
#pragma unroll
        for (int nt = 0; nt < 4; nt++) {
            const int ncol = wn + nt * 8 + cc;
            const float a0 = acc[mt][nt][0] * oscale, a1 = acc[mt][nt][1] * oscale;
            const float a2 = acc[mt][nt][2] * oscale, a3 = acc[mt][nt][3] * oscale;
            if (z < 2) {   // Q or K: (B,H,T,DH) bf16 hi/lo
                bf16* hi = (z == 0) ? qhi : khi;
                bf16* lo = (z == 0) ? qlo : klo;
                const size_t base = ((size_t)((b * H_ + h) * T_ + t)) * DH_ + ncol;
                u32 h01, l01, h23, l23;
                split2(a0, a1, h01, l01);
                split2(a2, a3, h23, l23);
                *(u32*)&hi[base] = h01;
                *(u32*)&lo[base] = l01;
                *(u32*)&hi[base + 8 * DH_] = h23;
                *(u32*)&lo[base + 8 * DH_] = l23;
            } else {       // V: transposed (B,H,DH,T) bf16 hi/lo
                const size_t r0b = ((size_t)((b * H_ + h) * DH_ + ncol)) * T_;
                const size_t r1b = r0b + T_;
                const float f[4] = {a0, a1, a2, a3};
                const size_t ix[4] = {r0b + t, r1b + t, r0b + t + 8, r1b + t + 8};
#pragma unroll
                for (int e = 0; e < 4; e++) {
                    const bf16 hv = __float2bfloat16(f[e]);
                    vthi[ix[e]] = hv;
                    vtlo[ix[e]] = __float2bfloat16(f[e] - __bfloat162float(hv));
                }
            }
        }
    }
}

// ---- output projection: fp16 2-product, f32 row-major out -------------------
__global__ __launch_bounds__(256) void o_gemm(
    const f16* __restrict__ Ah16, const f16* __restrict__ Al16,
    const f16* __restrict__ Wh16, float* __restrict__ Y) {
    GEMM_PROLOG();
    GEMM_MAINLOOP_F16();

    const int r  = lane >> 2;
    const int cc = (lane & 3) * 2;
#pragma unroll
    for (int mt = 0; mt < 2; mt++) {
        const int mrow = m0 + wm + mt * 16 + r;
#pragma unroll
        for (int nt = 0; nt < 4; nt++) {
            const int ncol = wn + nt * 8 + cc;
            *(float2*)&Y[(size_t)mrow * 1024 + n0 + ncol] =
                make_float2(acc[mt][nt][0], acc[mt][nt][1]);
            *(float2*)&Y[(size_t)(mrow + 8) * 1024 + n0 + ncol] =
                make_float2(acc[mt][nt][2], acc[mt][nt][3]);
        }
    }
}

// ---------------------------------------------------------------------------
// Pipelined HMMA flash attention (validated) — epilogue now writes fp16 hi/lo.
// ---------------------------------------------------------------------------
#define QSTR 72
#define VSTR 136
#define AQHI 0
#define AQLO 18432
#define ASTG 36864
#define SK_HI 0
#define SK_LO 18432
#define SV_HI 36864
#define SV_LO 54272
#define ASTG_SZ 71680
#define ATT_SMEM (ASTG + 2 * ASTG_SZ)   // 180224

__global__ __launch_bounds__(256, 1) void attn_hmma(
    const bf16* __restrict__ Qhi, const bf16* __restrict__ Qlo,
    const bf16* __restrict__ Khi, const bf16* __restrict__ Klo,
    const bf16* __restrict__ VThi, const bf16* __restrict__ VTlo,
    f16* __restrict__ Ohi, f16* __restrict__ Olo) {
    extern __shared__ __align__(16) char smc[];
    const u32 sb = smem_u32(smc);

    const int qb = gridDim.x - 1 - blockIdx.x;
    const int bh = blockIdx.y;
    const int tid  = threadIdx.x;
    const int wid  = tid >> 5;
    const int lane = tid & 31;
    const int wq = wid * 16;

    const bf16* Kg0 = Khi + (size_t)bh * T_ * DH_;
    const bf16* Kg1 = Klo + (size_t)bh * T_ * DH_;
    const bf16* Vg0 = VThi + (size_t)bh * DH_ * T_;
    const bf16* Vg1 = VTlo + (size_t)bh * DH_ * T_;

    auto stage_kv = [&](int kb, int s) {
        const u32 st = sb + ASTG + (u32)(s * ASTG_SZ);
#pragma unroll
        for (int it = 0; it < 4; it++) {
            const int c = tid + it * 256;
            {
                const int row = c >> 3, c16 = (c & 7) * 8;
                const size_t gi = (size_t)(kb * 128 + row) * DH_ + c16;
                const u32 so = (u32)((row * QSTR + c16) * 2);
                cpasync16(st + SK_HI + so, Kg0 + gi);
                cpasync16(st + SK_LO + so, Kg1 + gi);
            }
            {
                const int row = c >> 4, c16 = (c & 15) * 8;
                const size_t gi = (size_t)row * T_ + kb * 128 + c16;
                const u32 so = (u32)((row * VSTR + c16) * 2);
                cpasync16(st + SV_HI + so, Vg0 + gi);
                cpasync16(st + SV_LO + so, Vg1 + gi);
            }
        }
    };

    const bf16* Qg0 = Qhi + ((size_t)bh * T_ + qb * 128) * DH_;
    const bf16* Qg1 = Qlo + ((size_t)bh * T_ + qb * 128) * DH_;
#pragma unroll
    for (int it = 0; it < 4; it++) {
        const int c = tid + it * 256;
        const int row = c >> 3;
        const int k8  = (c & 7) * 8;
        *(uint4*)(smc + AQHI + (row * QSTR + k8) * 2) = *(const uint4*)&Qg0[row * 64 + k8];
        *(uint4*)(smc + AQLO + (row * QSTR + k8) * 2) = *(const uint4*)&Qg1[row * 64 + k8];
    }
    stage_kv(0, 0); CP_COMMIT();
    __syncthreads();

    const int aRow = lane & 15;
    const int aK   = (lane >> 4) * 8;
    const u32 qa = sb + AQHI + ((wq + aRow) * QSTR + aK) * 2;
    u32 qf[2][4][4];
#pragma unroll
    for (int ks = 0; ks < 4; ks++) {
        ldsm4(qf[0][ks][0], qf[0][ks][1], qf[0][ks][2], qf[0][ks][3], qa + ks * 32);
        ldsm4(qf[1][ks][0], qf[1][ks][1], qf[1][ks][2], qf[1][ks][3],
              qa + (AQLO - AQHI) + ks * 32);
    }

    float oacc[8][4];
#pragma unroll
    for (int nt = 0; nt < 8; nt++)
#pragma unroll
        for (int r = 0; r < 4; r++) oacc[nt][r] = 0.f;
    float mrw[2] = {-1e30f, -1e30f}, lrw[2] = {0.f, 0.f};

    const int bN = ((lane >> 4) << 3) | (lane & 7);
    const int bK = ((lane >> 3) & 1) * 8;
    const u32 kOff = (u32)((bN * QSTR + bK) * 2);
    const u32 vOff = (u32)((bN * VSTR + bK) * 2);
    const int r0 = lane >> 2;
    const int cb = (lane & 3) * 2;

    for (int kb = 0; kb <= qb; kb++) {
        CP_WAIT(0);
        __syncthreads();
        if (kb + 1 <= qb) { stage_kv(kb + 1, (kb + 1) & 1); CP_COMMIT(); }

        const u32 st = sb + ASTG + (u32)((kb & 1) * ASTG_SZ);
        const u32 kba = st + SK_HI + kOff;
        const u32 vba = st + SV_HI + vOff;

        float sacc[16][4];
#pragma unroll
        for (int nt = 0; nt < 16; nt++)
#pragma unroll
            for (int r = 0; r < 4; r++) sacc[nt][r] = 0.f;

#pragma unroll
        for (int nc = 0; nc < 8; nc++) {
            const u32 nco = (u32)(nc * 16 * QSTR * 2);
#pragma unroll
            for (int ks = 0; ks < 4; ks++) {
                u32 kh[4], kl[4];
                ldsm4(kh[0], kh[1], kh[2], kh[3], kba + nco + ks * 32);
                ldsm4(kl[0], kl[1], kl[2], kl[3],
                      kba + (SK_LO - SK_HI) + nco + ks * 32);
                mma16816(sacc[2 * nc],     qf[0][ks], &kh[0]);
                mma16816(sacc[2 * nc],     qf[0][ks], &kl[0]);
                mma16816(sacc[2 * nc],     qf[1][ks], &kh[0]);
                mma16816(sacc[2 * nc + 1], qf[0][ks], &kh[2]);
                mma16816(sacc[2 * nc + 1], qf[0][ks], &kl[2]);
                mma16816(sacc[2 * nc + 1], qf[1][ks], &kh[2]);
            }
        }

        const bool diag = (kb == qb);
        float alpha[2];
#pragma unroll
        for (int rh = 0; rh < 2; rh++) {
            const int rl = wq + r0 + rh * 8;
            float mx = -1e30f;
#pragma unroll
            for (int nt = 0; nt < 16; nt++) {
                float v0 = sacc[nt][2 * rh];
                float v1 = sacc[nt][2 * rh + 1];
                if (diag) {
                    const int col = nt * 8 + cb;
                    if (col > rl)     v0 = -1e30f;
                    if (col + 1 > rl) v1 = -1e30f;
                }
                sacc[nt][2 * rh]     = v0;
                sacc[nt][2 * rh + 1] = v1;
                mx = fmaxf(mx, fmaxf(v0, v1));
            }
            mx = fmaxf(mx, __shfl_xor_sync(0xffffffffu, mx, 1));
            mx = fmaxf(mx, __shfl_xor_sync(0xffffffffu, mx, 2));
            const float mnew = fmaxf(mrw[rh], mx);
            alpha[rh] = __expf(mrw[rh] - mnew);
            float rs = 0.f;
#pragma unroll
            for (int nt = 0; nt < 16; nt++) {
                const float p0 = __expf(sacc[nt][2 * rh]     - mnew);
                const float p1 = __expf(sacc[nt][2 * rh + 1] - mnew);
                sacc[nt][2 * rh]     = p0;
                sacc[nt][2 * rh + 1] = p1;
                rs += p0 + p1;
            }
            rs += __shfl_xor_sync(0xffffffffu, rs, 1);
            rs += __shfl_xor_sync(0xffffffffu, rs, 2);
            lrw[rh] = lrw[rh] * alpha[rh] + rs;
            mrw[rh] = mnew;
        }
#pragma unroll
        for (int nt = 0; nt < 8; nt++) {
            oacc[nt][0] *= alpha[0];
            oacc[nt][1] *= alpha[0];
            oacc[nt][2] *= alpha[1];
            oacc[nt][3] *= alpha[1];
        }

#pragma unroll
        for (int ks = 0; ks < 8; ks++) {
            u32 ph[4], pl[4];
            split2(sacc[2 * ks][0],     sacc[2 * ks][1],     ph[0], pl[0]);
            split2(sacc[2 * ks][2],     sacc[2 * ks][3],     ph[1], pl[1]);
            split2(sacc[2 * ks + 1][0], sacc[2 * ks + 1][1], ph[2], pl[2]);
            split2(sacc[2 * ks + 1][2], sacc[2 * ks + 1][3], ph[3], pl[3]);
#pragma unroll
            for (int nc = 0; nc < 4; nc++) {
                const u32 nco = (u32)(nc * 16 * VSTR * 2);
                u32 vh[4], vl[4];
                ldsm4(vh[0], vh[1], vh[2], vh[3], vba + nco + ks * 32);
                ldsm4(vl[0], vl[1], vl[2], vl[3],
                      vba + (SV_LO - SV_HI) + nco + ks * 32);
                mma16816(oacc[2 * nc],     ph, &vh[0]);
                mma16816(oacc[2 * nc],     ph, &vl[0]);
                mma16816(oacc[2 * nc],     pl, &vh[0]);
                mma16816(oacc[2 * nc + 1], ph, &vh[2]);
                mma16816(oacc[2 * nc + 1], ph, &vl[2]);
                mma16816(oacc[2 * nc + 1], pl, &vh[2]);
            }
        }
    }

    const float inv0 = 1.f / lrw[0];
    const float inv1 = 1.f / lrw[1];
    const int b  = bh >> 4;
    const int hh = bh & 15;
    const int t0 = qb * 128 + wq + r0;
#pragma unroll
    for (int nt = 0; nt < 8; nt++) {
        const int col = hh * 64 + nt * 8 + cb;
        u32 h01, l01, h23, l23;
        split2h(oacc[nt][0] * inv0, oacc[nt][1] * inv0, h01, l01);
        split2h(oacc[nt][2] * inv1, oacc[nt][3] * inv1, h23, l23);
        const size_t i0 = ((size_t)(b * T_ + t0)) * D_ + col;
        const size_t i1 = ((size_t)(b * T_ + t0 + 8)) * D_ + col;
        *(u32*)&Ohi[i0] = h01;
        *(u32*)&Olo[i0] = l01;
        *(u32*)&Ohi[i1] = h23;
        *(u32*)&Olo[i1] = l23;
    }
}

// ---------------------------------------------------------------------------
// Host launcher (graph-capturable)
// ---------------------------------------------------------------------------
extern "C" void kernel_launch(void* const* d_in, const int* in_sizes, int n_in,
                              void* d_out, int out_size) {
    (void)in_sizes; (void)n_in; (void)out_size;
    const float* x  = (const float*)d_in[0];
    const float* Wq = (const float*)d_in[1];
    const float* Wk = (const float*)d_in[2];
    const float* Wv = (const float*)d_in[3];
    const float* Wo = (const float*)d_in[4];
    float* out = (float*)d_out;

    bf16 *xbhi, *xblo, *wT, *qhi, *qlo, *khi, *klo, *vthi, *vtlo;
    f16  *xh16, *xl16, *w16, *ah16, *al16;
    cudaGetSymbolAddress((void**)&xbhi, g_xhi);
    cudaGetSymbolAddress((void**)&xblo, g_xlo);
    cudaGetSymbolAddress((void**)&xh16, g_xh16);
    cudaGetSymbolAddress((void**)&xl16, g_xl16);
    cudaGetSymbolAddress((void**)&wT,   g_wT);
    cudaGetSymbolAddress((void**)&w16,  g_w16);
    cudaGetSymbolAddress((void**)&qhi,  g_qhi);
    cudaGetSymbolAddress((void**)&qlo,  g_qlo);
    cudaGetSymbolAddress((void**)&khi,  g_khi);
    cudaGetSymbolAddress((void**)&klo,  g_klo);
    cudaGetSymbolAddress((void**)&vthi, g_vthi);
    cudaGetSymbolAddress((void**)&vtlo, g_vtlo);
    cudaGetSymbolAddress((void**)&ah16, g_ah16);
    cudaGetSymbolAddress((void**)&al16, g_al16);

    cudaFuncSetAttribute(qkv_gemm, cudaFuncAttributeMaxDynamicSharedMemorySize, GS_TOT);
    cudaFuncSetAttribute(o_gemm,   cudaFuncAttributeMaxDynamicSharedMemorySize, GS_TOT);
    cudaFuncSetAttribute(attn_hmma, cudaFuncAttributeMaxDynamicSharedMemorySize, ATT_SMEM);

    // --- pre-pass (2 launches) ---
    split_kernel<<<M_ * D_ / 1024, 256>>>(x, xbhi, xblo, xh16, xl16);
    const dim3 tgrid(D_ / 32, D_ / 32, 4);
    tsplit_kernel<<<tgrid, 256>>>(Wq, Wk, Wv, Wo, wT, w16);

    // --- Q,K,V projections in ONE launch ---
    const dim3 qkvgrid(D_ / 64, M_ / 128, 3);
    qkv_gemm<<<qkvgrid, 256, GS_TOT>>>(xbhi, xblo, xh16, xl16, wT, w16,
                                       qhi, qlo, khi, klo, vthi, vtlo);

    // --- attention ---
    const dim3 agrid(T_ / 128, BH_);
    attn_hmma<<<agrid, 256, ATT_SMEM>>>(qhi, qlo, khi, klo, vthi, vtlo, ah16, al16);

    // --- output projection (fp16 2-product) ---
    const dim3 ogrid(D_ / 64, M_ / 128);
    o_gemm<<<ogrid, 256, GS_TOT>>>(ah16, al16, w16 + (size_t)D_ * D_, out);
}